// round 8
// baseline (speedup 1.0000x reference)
#include <cuda_runtime.h>
#include <math.h>

typedef unsigned long long ull;

#define GN 40000
#define PN 5
#define UVE 65536
#define TM 64
#define NT 625   // ceil(GN/TM)

__device__ __forceinline__ ull fma2(ull a, ull b, ull c) {
    ull d; asm("fma.rn.f32x2 %0, %1, %2, %3;" : "=l"(d) : "l"(a), "l"(b), "l"(c)); return d;
}
__device__ __forceinline__ ull pack2(float lo, float hi) {
    ull d; asm("mov.b64 %0, {%1, %2};" : "=l"(d) : "f"(lo), "f"(hi)); return d;
}
__device__ __forceinline__ void unpack2(ull v, float& lo, float& hi) {
    asm("mov.b64 {%0, %1}, %2;" : "=f"(lo), "=f"(hi) : "l"(v));
}

// ---------- scratch ----------
__device__ int    g_counts[8];
__device__ int    g_offsets[8];
__device__ int    g_cursor[8];
__device__ int    g_order[GN];
__device__ float  g_uvmap[32 * UVE];
__device__ float  g_bufA[64 * UVE];
__device__ float  g_bufB[64 * UVE];
__device__ float  g_mean[64];
__device__ float  g_invstd[64];
__device__ float  g_psum[64 * 256];
__device__ float  g_psumsq[64 * 256];
__device__ float2 g_wt[130752];   // in[cin32][co64][9]@0 ; hid[l][cin64][co64][9]@18432 ; out[cin64][co3][9]@129024

// ---------- bucketing (3-kernel, measured-good) ----------
__global__ void count_k(const int* __restrict__ part, int* counts) {
    int g = blockIdx.x * blockDim.x + threadIdx.x;
    if (g < GN) atomicAdd(&counts[part[g]], 1);
}
__global__ void scan_k(const int* __restrict__ counts, int* offsets, int* cursor) {
    if (threadIdx.x == 0) {
        int s = 0;
        for (int p = 0; p < PN; p++) { offsets[p] = s; cursor[p] = s; s += counts[p]; }
        offsets[PN] = s;
    }
}
__global__ void scatter_k(const int* __restrict__ part, int* cursor, int* __restrict__ order) {
    int g = blockIdx.x * blockDim.x + threadIdx.x;
    if (g < GN) { int pos = atomicAdd(&cursor[part[g]], 1); order[pos] = g; }
}

// ---------- conv weight transpose + duplicate ----------
__global__ void wprep_k(const float* __restrict__ win, const float* __restrict__ whid,
                        const float* __restrict__ wout, float2* __restrict__ wt) {
    int i = blockIdx.x * 256 + threadIdx.x;
    if (i < 18432) {              // [cin32][co64][9] <- OIHW [64][32][9]
        int k = i % 9; int t = i / 9; int co = t % 64, cin = t / 64;
        float v = win[(co * 32 + cin) * 9 + k];
        wt[i] = make_float2(v, v);
    }
    if (i < 110592) {             // [l][cin64][co64][9] <- [l][64][64][9]
        int k = i % 9; int t = i / 9; int co = t % 64;
        int t2 = t / 64; int cin = t2 % 64, l = t2 / 64;
        float v = whid[((l * 64 + co) * 64 + cin) * 9 + k];
        wt[18432 + i] = make_float2(v, v);
    }
    if (i < 1728) {               // [cin64][co3][9] <- [3][64][9]
        int k = i % 9; int t = i / 9; int co = t % 3, cin = t / 3;
        float v = wout[(co * 64 + cin) * 9 + k];
        wt[129024 + i] = make_float2(v, v);
    }
}

// ---------- fused MLP (TM=64, col-packed f32x2, double-buffered weights) ----------
template<int MODE>  // 0: lrelu->Out  1: masked cols->Out  2: masked, scatter uvmap
__device__ __forceinline__ void layer2(
    const float* A, int K, int NC,
    const float* __restrict__ W, int N, const float* __restrict__ bias,
    float* Out, float* Bs, int tid,
    const int* s_uv, float* uvmap, int m)
{
    const int w = tid >> 5, lane = tid & 31;
    const int r0 = (lane & 15) << 2;
    const int c0 = (w << 4) + ((lane >> 4) << 3);
    const bool active = (w << 4) < N;

    ull acc[4][4];
#pragma unroll
    for (int r = 0; r < 4; r++)
#pragma unroll
        for (int cp = 0; cp < 4; cp++) acc[r][cp] = 0ull;

    float wpf[8];
#pragma unroll
    for (int t = 0; t < 8; t++) {
        int e = tid + (t << 8); int kk = e >> 7, j = e & 127;
        wpf[t] = (kk < K && j < N) ? W[kk * N + j] : 0.f;
    }

    for (int ch = 0; ch < NC; ch++) {
        float* B = Bs + ((ch & 1) << 11);
#pragma unroll
        for (int t = 0; t < 8; t++) B[tid + (t << 8)] = wpf[t];
        __syncthreads();
        if (ch + 1 < NC) {
            int kb = (ch + 1) << 4;
#pragma unroll
            for (int t = 0; t < 8; t++) {
                int e = tid + (t << 8); int kk = kb + (e >> 7), j = e & 127;
                wpf[t] = (kk < K && j < N) ? W[kk * N + j] : 0.f;
            }
        }
        if (active) {
            const float* Ak = A + (ch << 4) * TM + r0;
            const float* Bk = B + c0;
#pragma unroll
            for (int kk = 0; kk < 16; kk++) {
                float4 a4 = *(const float4*)(Ak + (kk << 6));
                ulonglong2 b01 = *(const ulonglong2*)(Bk + (kk << 7));
                ulonglong2 b23 = *(const ulonglong2*)(Bk + (kk << 7) + 4);
                ull ar[4] = { pack2(a4.x, a4.x), pack2(a4.y, a4.y),
                              pack2(a4.z, a4.z), pack2(a4.w, a4.w) };
                ull bp[4] = { b01.x, b01.y, b23.x, b23.y };
#pragma unroll
                for (int r = 0; r < 4; r++)
#pragma unroll
                    for (int cp = 0; cp < 4; cp++)
                        acc[r][cp] = fma2(ar[r], bp[cp], acc[r][cp]);
            }
        }
    }

    if (active) {
#pragma unroll
        for (int cp = 0; cp < 4; cp++) {
            int c = c0 + (cp << 1);
            float lo, hi;
            if (MODE == 0) {
                float blo = bias[c], bhi = bias[c + 1];
#pragma unroll
                for (int r = 0; r < 4; r++) {
                    unpack2(acc[r][cp], lo, hi);
                    lo += blo; hi += bhi;
                    Out[c * TM + r0 + r]       = lo > 0.f ? lo : 0.01f * lo;
                    Out[(c + 1) * TM + r0 + r] = hi > 0.f ? hi : 0.01f * hi;
                }
            } else if (MODE == 1) {
#pragma unroll
                for (int r = 0; r < 4; r++) {
                    unpack2(acc[r][cp], lo, hi);
                    if (c < N)     Out[c * TM + r0 + r]       = lo + bias[c];
                    if (c + 1 < N) Out[(c + 1) * TM + r0 + r] = hi + bias[c + 1];
                }
            } else {
                float blo = bias[c], bhi = bias[c + 1];
#pragma unroll
                for (int r = 0; r < 4; r++) {
                    if (r0 + r < m) {
                        int uv = s_uv[r0 + r];
                        unpack2(acc[r][cp], lo, hi);
                        uvmap[c * UVE + uv]       = lo + blo;
                        uvmap[(c + 1) * UVE + uv] = hi + bhi;
                    }
                }
            }
        }
    }
    __syncthreads();
}

__global__ __launch_bounds__(256, 2)
void mlp_k(const float* __restrict__ latent_z, const float* __restrict__ latent_f,
           const float* __restrict__ cano_xyz,
           const float* __restrict__ m1_w_in, const float* __restrict__ m1_b_in,
           const float* __restrict__ m1_w_hid, const float* __restrict__ m1_b_hid,
           const float* __restrict__ m1_w_out, const float* __restrict__ m1_b_out,
           const float* __restrict__ m2_w_in, const float* __restrict__ m2_b_in,
           const float* __restrict__ m2_w_hid, const float* __restrict__ m2_b_hid,
           const float* __restrict__ m2_w_out, const float* __restrict__ m2_b_out,
           const int* __restrict__ uv_idx,
           const int* __restrict__ order, const int* __restrict__ offsets,
           float* __restrict__ uvmap)
{
    extern __shared__ float sm[];
    float* Xs = sm;                        // [112][64]
    float* Hp = Xs + 112 * TM;             // [128][64]
    float* Hq = Hp + 128 * TM;             // [128][64]
    float* Bs = Hq + 128 * TM;             // [2][2048]
    int*   s_idx = (int*)(Bs + 4096);      // [64]
    int*   s_uv  = s_idx + TM;             // [64]

    int p = blockIdx.x / NT;
    int t = blockIdx.x % NT;
    int beg = offsets[p], end = offsets[p + 1];
    int start = beg + t * TM;
    if (start >= end) return;
    int m = min(TM, end - start);
    int tid = threadIdx.x;

    if (tid < TM) {
        int rr = tid < m ? tid : (m - 1);
        int gid = order[start + rr];
        s_idx[tid] = gid;
        s_uv[tid] = uv_idx[gid];
    }
    __syncthreads();

    for (int e = tid; e < 112 * TM; e += 256) {
        int d = e >> 6, r = e & 63;
        float v = 0.f;
        if (d < 64)       v = latent_f[p * 64 + d];
        else if (d < 96)  v = latent_z[s_idx[r] * 32 + (d - 64)];
        else if (d < 99)  v = cano_xyz[s_idx[r] * 3 + (d - 96)];
        Xs[e] = v;
    }

    layer2<0>(Xs, 96, 6,  m1_w_in  + p * 96 * 128, 128, m1_b_in  + p * 128, Hp, Bs, tid, 0, 0, m);
    layer2<0>(Hp, 128, 8, m1_w_hid + (p * 2 + 0) * 16384, 128, m1_b_hid + (p * 2 + 0) * 128, Hq, Bs, tid, 0, 0, m);
    layer2<0>(Hq, 128, 8, m1_w_hid + (p * 2 + 1) * 16384, 128, m1_b_hid + (p * 2 + 1) * 128, Hp, Bs, tid, 0, 0, m);
    layer2<1>(Hp, 128, 8, m1_w_out + p * 128 * 11, 11, m1_b_out + p * 11, Xs + 99 * TM, Bs, tid, 0, 0, m);
    layer2<0>(Xs, 110, 7, m2_w_in  + p * 110 * 128, 128, m2_b_in  + p * 128, Hp, Bs, tid, 0, 0, m);
    layer2<0>(Hp, 128, 8, m2_w_hid + (p * 2 + 0) * 16384, 128, m2_b_hid + (p * 2 + 0) * 128, Hq, Bs, tid, 0, 0, m);
    layer2<0>(Hq, 128, 8, m2_w_hid + (p * 2 + 1) * 16384, 128, m2_b_hid + (p * 2 + 1) * 128, Hp, Bs, tid, 0, 0, m);
    layer2<2>(Hp, 128, 8, m2_w_out + p * 128 * 32, 32, m2_b_out + p * 32, (float*)0, Bs, tid, s_uv, uvmap, m);
}

// ---------- CNN ----------
template<bool NORM, bool RELU, int TW>
__device__ __forceinline__ float conv_val(const float* __restrict__ in, int cin,
                                          int x0, int y0, int e, float mn, float is) {
    int row = e / TW, col = e - row * TW;
    int iy = y0 + row - 1, ix = x0 + col - 1;
    float v = 0.f;
    if (iy >= 0 && iy < 256 && ix >= 0 && ix < 256) {
        v = in[cin * UVE + iy * 256 + ix];
        if (NORM) v = (v - mn) * is;
        if (RELU) v = fmaxf(v, 0.f);
    }
    return v;
}

// 16x16 px x 64 co per block. Thread: 2x4 px (pg=tid&31) x 8 co (cg=tid>>5, warp-uniform).
// 2-cin rounds, double-buffered; one barrier per 2 cins. f32x2 over px pairs.
template<int CIN, bool RELU, bool NORM, bool STATS>
__global__ __launch_bounds__(256, 2)
void conv64_k(const float* __restrict__ in, const float2* __restrict__ wt,
              const float* __restrict__ bias,
              const float* __restrict__ mean, const float* __restrict__ invstd,
              float* __restrict__ out,
              float* __restrict__ psum, float* __restrict__ psumsq)
{
    __shared__ __align__(16) float tA[2][2][324];
    __shared__ __align__(16) float tB[2][2][328];
    __shared__ __align__(16) float2 ws[2][2][576];

    const int bx = blockIdx.x;
    const int x0 = (bx & 15) << 4, y0 = (bx >> 4) << 4;
    const int tid = threadIdx.x;
    const int pg = tid & 31, cg = tid >> 5;
    const int lx = (pg & 3) << 2, ly = (pg >> 2) << 1;

    ull acc[8][4];
#pragma unroll
    for (int co = 0; co < 8; co++)
#pragma unroll
        for (int q = 0; q < 4; q++) acc[co][q] = 0ull;

    for (int rnd = 0; rnd < CIN / 2; rnd++) {
        const int b = rnd & 1;
#pragma unroll
        for (int cc = 0; cc < 2; cc++) {
            const int cin = rnd * 2 + cc;
            float mn = NORM ? mean[cin] : 0.f, is = NORM ? invstd[cin] : 1.f;
            float v0 = conv_val<NORM, RELU, 18>(in, cin, x0, y0, tid, mn, is);
            tA[b][cc][tid] = v0; tB[b][cc][tid + 1] = v0;
            if (tid < 68) {
                float v1 = conv_val<NORM, RELU, 18>(in, cin, x0, y0, tid + 256, mn, is);
                tA[b][cc][tid + 256] = v1; tB[b][cc][tid + 257] = v1;
            }
            const float2* wp = wt + cin * 576;
            ws[b][cc][tid] = wp[tid];
            ws[b][cc][tid + 256] = wp[tid + 256];
            if (tid < 64) ws[b][cc][tid + 512] = wp[tid + 512];
        }
        __syncthreads();
#pragma unroll
        for (int cc = 0; cc < 2; cc++) {
            ull pp[4][5];
#pragma unroll
            for (int r = 0; r < 4; r++) {
                int base = (ly + r) * 18 + lx;
                pp[r][0] = *(const ull*)&tA[b][cc][base];
                pp[r][1] = *(const ull*)&tB[b][cc][base + 2];
                pp[r][2] = *(const ull*)&tA[b][cc][base + 2];
                pp[r][3] = *(const ull*)&tB[b][cc][base + 4];
                pp[r][4] = *(const ull*)&tA[b][cc][base + 4];
            }
            const float2* wpp = ws[b][cc] + (cg << 3) * 9;
#pragma unroll
            for (int co = 0; co < 8; co++)
#pragma unroll
                for (int ky = 0; ky < 3; ky++)
#pragma unroll
                    for (int kx = 0; kx < 3; kx++) {
                        ull w2 = *(const ull*)&wpp[co * 9 + ky * 3 + kx];
                        acc[co][0] = fma2(pp[ky][kx],         w2, acc[co][0]);
                        acc[co][1] = fma2(pp[ky][kx + 2],     w2, acc[co][1]);
                        acc[co][2] = fma2(pp[ky + 1][kx],     w2, acc[co][2]);
                        acc[co][3] = fma2(pp[ky + 1][kx + 2], w2, acc[co][3]);
                    }
        }
        // no barrier here: next round's staging targets the other buffer, and
        // reaching it requires passing this round's barrier (safe by induction)
    }

#pragma unroll
    for (int co = 0; co < 8; co++) {
        int c = (cg << 3) + co;
        float bb = bias[c];
        float v0, v1, v2, v3, v4, v5, v6, v7;
        unpack2(acc[co][0], v0, v1); unpack2(acc[co][1], v2, v3);
        unpack2(acc[co][2], v4, v5); unpack2(acc[co][3], v6, v7);
        v0 += bb; v1 += bb; v2 += bb; v3 += bb;
        v4 += bb; v5 += bb; v6 += bb; v7 += bb;
        float* op = out + c * UVE + (y0 + ly) * 256 + (x0 + lx);
        *(float4*)op         = make_float4(v0, v1, v2, v3);
        *(float4*)(op + 256) = make_float4(v4, v5, v6, v7);
        if (STATS) {
            float s = v0 + v1 + v2 + v3 + v4 + v5 + v6 + v7;
            float q = v0 * v0 + v1 * v1 + v2 * v2 + v3 * v3
                    + v4 * v4 + v5 * v5 + v6 * v6 + v7 * v7;
#pragma unroll
            for (int d = 16; d >= 1; d >>= 1) {
                s += __shfl_down_sync(0xffffffffu, s, d);
                q += __shfl_down_sync(0xffffffffu, q, d);
            }
            if (pg == 0) {
                psum[c * 256 + bx] = s;
                psumsq[c * 256 + bx] = q;
            }
        }
    }
}

__global__ void finalize_k(const float* __restrict__ psum, const float* __restrict__ psumsq,
                           float* __restrict__ mean, float* __restrict__ invstd) {
    __shared__ float s1[256], s2[256];
    int c = blockIdx.x, tid = threadIdx.x;
    s1[tid] = psum[c * 256 + tid];
    s2[tid] = psumsq[c * 256 + tid];
    __syncthreads();
    for (int s = 128; s > 0; s >>= 1) {
        if (tid < s) { s1[tid] += s1[tid + s]; s2[tid] += s2[tid + s]; }
        __syncthreads();
    }
    if (tid == 0) {
        float mu = s1[0] * (1.f / UVE);
        float var = s2[0] * (1.f / UVE) - mu * mu;
        mean[c] = mu;
        invstd[c] = rsqrtf(var + 1e-5f);
    }
}

// conv_out: 64 -> 3, normalized input, sigmoid. Block 32x16 px; thread = 1 px pair x 3 couts.
__global__ __launch_bounds__(256, 2)
void convout_k(const float* __restrict__ in, const float2* __restrict__ wt,
               const float* __restrict__ bias,
               const float* __restrict__ mean, const float* __restrict__ invstd,
               float* __restrict__ out)
{
    __shared__ __align__(16) float tA[2][612];
    __shared__ __align__(16) float tB[2][616];
    __shared__ __align__(16) float2 wds[1728];

    const int bx = blockIdx.x;
    const int x0 = (bx & 7) << 5, y0 = (bx >> 3) << 4;
    const int tid = threadIdx.x;
    const int lx = (tid & 15) << 1, ly = tid >> 4;

    for (int e = tid; e < 1728; e += 256) wds[e] = wt[e];

    ull acc0 = 0ull, acc1 = 0ull, acc2 = 0ull;

    float tv0, tv1 = 0.f, tv2 = 0.f;
    {
        float mn = mean[0], is = invstd[0];
        tv0 = conv_val<true, false, 34>(in, 0, x0, y0, tid, mn, is);
        tv1 = conv_val<true, false, 34>(in, 0, x0, y0, tid + 256, mn, is);
        if (tid < 100) tv2 = conv_val<true, false, 34>(in, 0, x0, y0, tid + 512, mn, is);
    }

    for (int cin = 0; cin < 64; cin++) {
        const int b = cin & 1;
        tA[b][tid] = tv0; tB[b][tid + 1] = tv0;
        tA[b][tid + 256] = tv1; tB[b][tid + 257] = tv1;
        if (tid < 100) { tA[b][tid + 512] = tv2; tB[b][tid + 513] = tv2; }
        __syncthreads();
        if (cin + 1 < 64) {
            int c2 = cin + 1;
            float mn = mean[c2], is = invstd[c2];
            tv0 = conv_val<true, false, 34>(in, c2, x0, y0, tid, mn, is);
            tv1 = conv_val<true, false, 34>(in, c2, x0, y0, tid + 256, mn, is);
            if (tid < 100) tv2 = conv_val<true, false, 34>(in, c2, x0, y0, tid + 512, mn, is);
        }
        ull pp[3][3];
#pragma unroll
        for (int r = 0; r < 3; r++) {
            int base = (ly + r) * 34 + lx;
            pp[r][0] = *(const ull*)&tA[b][base];
            pp[r][1] = *(const ull*)&tB[b][base + 2];
            pp[r][2] = *(const ull*)&tA[b][base + 2];
        }
        const float2* wc = wds + cin * 27;
#pragma unroll
        for (int r = 0; r < 3; r++)
#pragma unroll
            for (int kx = 0; kx < 3; kx++) {
                acc0 = fma2(pp[r][kx], *(const ull*)&wc[r * 3 + kx],      acc0);
                acc1 = fma2(pp[r][kx], *(const ull*)&wc[9 + r * 3 + kx],  acc1);
                acc2 = fma2(pp[r][kx], *(const ull*)&wc[18 + r * 3 + kx], acc2);
            }
        __syncthreads();
    }

    int o = (y0 + ly) * 256 + x0 + lx;
    float lo, hi;
    unpack2(acc0, lo, hi);
    *(float2*)(out + o) = make_float2(1.f / (1.f + __expf(-(lo + bias[0]))),
                                      1.f / (1.f + __expf(-(hi + bias[0]))));
    unpack2(acc1, lo, hi);
    *(float2*)(out + UVE + o) = make_float2(1.f / (1.f + __expf(-(lo + bias[1]))),
                                            1.f / (1.f + __expf(-(hi + bias[1]))));
    unpack2(acc2, lo, hi);
    *(float2*)(out + 2 * UVE + o) = make_float2(1.f / (1.f + __expf(-(lo + bias[2]))),
                                                1.f / (1.f + __expf(-(hi + bias[2]))));
}

// ---------- launch ----------
extern "C" void kernel_launch(void* const* d_in, const int* in_sizes, int n_in,
                              void* d_out, int out_size)
{
    const float* latent_z  = (const float*)d_in[0];
    const float* latent_f  = (const float*)d_in[1];
    const float* cano_xyz  = (const float*)d_in[2];
    const float* m1_w_in   = (const float*)d_in[3];
    const float* m1_b_in   = (const float*)d_in[4];
    const float* m1_w_hid  = (const float*)d_in[5];
    const float* m1_b_hid  = (const float*)d_in[6];
    const float* m1_w_out  = (const float*)d_in[7];
    const float* m1_b_out  = (const float*)d_in[8];
    const float* m2_w_in   = (const float*)d_in[9];
    const float* m2_b_in   = (const float*)d_in[10];
    const float* m2_w_hid  = (const float*)d_in[11];
    const float* m2_b_hid  = (const float*)d_in[12];
    const float* m2_w_out  = (const float*)d_in[13];
    const float* m2_b_out  = (const float*)d_in[14];
    const float* conv_in_w = (const float*)d_in[15];
    const float* conv_in_b = (const float*)d_in[16];
    const float* conv_hid_w= (const float*)d_in[17];
    const float* conv_hid_b= (const float*)d_in[18];
    const float* conv_out_w= (const float*)d_in[19];
    const float* conv_out_b= (const float*)d_in[20];
    const int*   gs_part   = (const int*)d_in[21];
    const int*   uv_idx    = (const int*)d_in[22];
    float* outp = (float*)d_out;

    void *p_counts, *p_offsets, *p_cursor, *p_order, *p_uvmap, *p_bufA, *p_bufB;
    void *p_mean, *p_invstd, *p_wt, *p_ps, *p_pq;
    cudaGetSymbolAddress(&p_counts, g_counts);
    cudaGetSymbolAddress(&p_offsets, g_offsets);
    cudaGetSymbolAddress(&p_cursor, g_cursor);
    cudaGetSymbolAddress(&p_order, g_order);
    cudaGetSymbolAddress(&p_uvmap, g_uvmap);
    cudaGetSymbolAddress(&p_bufA, g_bufA);
    cudaGetSymbolAddress(&p_bufB, g_bufB);
    cudaGetSymbolAddress(&p_mean, g_mean);
    cudaGetSymbolAddress(&p_invstd, g_invstd);
    cudaGetSymbolAddress(&p_wt, g_wt);
    cudaGetSymbolAddress(&p_ps, g_psum);
    cudaGetSymbolAddress(&p_pq, g_psumsq);

    cudaMemsetAsync(p_counts, 0, 8 * sizeof(int), 0);
    cudaMemsetAsync(p_uvmap, 0, 32 * UVE * sizeof(float), 0);

    wprep_k<<<432, 256>>>(conv_in_w, conv_hid_w, conv_out_w, (float2*)p_wt);

    int gb = (GN + 255) / 256;
    count_k<<<gb, 256>>>(gs_part, (int*)p_counts);
    scan_k<<<1, 32>>>((const int*)p_counts, (int*)p_offsets, (int*)p_cursor);
    scatter_k<<<gb, 256>>>(gs_part, (int*)p_cursor, (int*)p_order);

    static bool attr_set = false;
    if (!attr_set) {
        cudaFuncSetAttribute(mlp_k, cudaFuncAttributeMaxDynamicSharedMemorySize, 111104);
        attr_set = true;
    }
    mlp_k<<<PN * NT, 256, 111104>>>(
        latent_z, latent_f, cano_xyz,
        m1_w_in, m1_b_in, m1_w_hid, m1_b_hid, m1_w_out, m1_b_out,
        m2_w_in, m2_b_in, m2_w_hid, m2_b_hid, m2_w_out, m2_b_out,
        uv_idx, (const int*)p_order, (const int*)p_offsets, (float*)p_uvmap);

    float* bufA = (float*)p_bufA;
    float* bufB = (float*)p_bufB;
    float* mean = (float*)p_mean;
    float* invstd = (float*)p_invstd;
    float* ps = (float*)p_ps;
    float* pq = (float*)p_pq;
    const float2* wt = (const float2*)p_wt;

    conv64_k<32, false, false, false><<<256, 256>>>((const float*)p_uvmap, wt, conv_in_b, 0, 0, bufA, 0, 0);
    conv64_k<64, true, false, true><<<256, 256>>>(bufA, wt + 18432, conv_hid_b, 0, 0, bufB, ps, pq);
    finalize_k<<<64, 256>>>(ps, pq, mean, invstd);
    conv64_k<64, true, true, true><<<256, 256>>>(bufB, wt + 18432 + 36864, conv_hid_b + 64, mean, invstd, bufA, ps, pq);
    finalize_k<<<64, 256>>>(ps, pq, mean, invstd);
    conv64_k<64, true, true, true><<<256, 256>>>(bufA, wt + 18432 + 2 * 36864, conv_hid_b + 128, mean, invstd, bufB, ps, pq);
    finalize_k<<<64, 256>>>(ps, pq, mean, invstd);
    convout_k<<<128, 256>>>(bufB, wt + 129024, conv_out_b, mean, invstd, outp);
}

// round 9
// speedup vs baseline: 1.1397x; 1.1397x over previous
#include <cuda_runtime.h>
#include <math.h>

typedef unsigned long long ull;

#define GN 40000
#define PN 5
#define UVE 65536
#define TM 64
#define NT 625   // ceil(GN/TM)

__device__ __forceinline__ ull fma2(ull a, ull b, ull c) {
    ull d; asm("fma.rn.f32x2 %0, %1, %2, %3;" : "=l"(d) : "l"(a), "l"(b), "l"(c)); return d;
}
__device__ __forceinline__ ull pack2(float lo, float hi) {
    ull d; asm("mov.b64 %0, {%1, %2};" : "=l"(d) : "f"(lo), "f"(hi)); return d;
}
__device__ __forceinline__ void unpack2(ull v, float& lo, float& hi) {
    asm("mov.b64 {%0, %1}, %2;" : "=f"(lo), "=f"(hi) : "l"(v));
}

// ---------- scratch ----------
__device__ int    g_counts[8];
__device__ int    g_offsets[8];
__device__ int    g_cursor[8];
__device__ int    g_order[GN];
__device__ float  g_uvmap[32 * UVE];
__device__ float  g_bufA[64 * UVE];
__device__ float  g_bufB[64 * UVE];
__device__ float  g_mean[64];
__device__ float  g_invstd[64];
__device__ float  g_psum[64 * 512];
__device__ float  g_psumsq[64 * 512];
__device__ float2 g_wt[130752];   // in[cin32][k9][co64]@0 ; hid[l][cin64][k9][co64]@18432 ; out[cin64][co3][9]@129024

// ---------- bucketing (3-kernel, measured-good) ----------
__global__ void count_k(const int* __restrict__ part, int* counts) {
    int g = blockIdx.x * blockDim.x + threadIdx.x;
    if (g < GN) atomicAdd(&counts[part[g]], 1);
}
__global__ void scan_k(const int* __restrict__ counts, int* offsets, int* cursor) {
    if (threadIdx.x == 0) {
        int s = 0;
        for (int p = 0; p < PN; p++) { offsets[p] = s; cursor[p] = s; s += counts[p]; }
        offsets[PN] = s;
    }
}
__global__ void scatter_k(const int* __restrict__ part, int* cursor, int* __restrict__ order) {
    int g = blockIdx.x * blockDim.x + threadIdx.x;
    if (g < GN) { int pos = atomicAdd(&cursor[part[g]], 1); order[pos] = g; }
}

// ---------- conv weight transpose + duplicate (k-major co layout) ----------
__global__ void wprep_k(const float* __restrict__ win, const float* __restrict__ whid,
                        const float* __restrict__ wout, float2* __restrict__ wt) {
    int i = blockIdx.x * 256 + threadIdx.x;
    if (i < 18432) {              // [cin32][k9][co64] <- OIHW [64][32][9]
        int k = i % 9; int t = i / 9; int co = t % 64, cin = t / 64;
        float v = win[(co * 32 + cin) * 9 + k];
        wt[cin * 576 + k * 64 + co] = make_float2(v, v);
    }
    if (i < 110592) {             // [l][cin64][k9][co64] <- [l][64][64][9]
        int k = i % 9; int t = i / 9; int co = t % 64;
        int t2 = t / 64; int cin = t2 % 64, l = t2 / 64;
        float v = whid[((l * 64 + co) * 64 + cin) * 9 + k];
        wt[18432 + l * 36864 + cin * 576 + k * 64 + co] = make_float2(v, v);
    }
    if (i < 1728) {               // [cin64][co3][9] <- [3][64][9] (convout keeps co-major)
        int k = i % 9; int t = i / 9; int co = t % 3, cin = t / 3;
        float v = wout[(co * 64 + cin) * 9 + k];
        wt[129024 + i] = make_float2(v, v);
    }
}

// ---------- fused MLP (TM=64, col-packed f32x2, double-buffered weights) ----------
template<int MODE>  // 0: lrelu->Out  1: masked cols->Out  2: masked, scatter uvmap
__device__ __forceinline__ void layer2(
    const float* A, int K, int NC,
    const float* __restrict__ W, int N, const float* __restrict__ bias,
    float* Out, float* Bs, int tid,
    const int* s_uv, float* uvmap, int m)
{
    const int w = tid >> 5, lane = tid & 31;
    const int r0 = (lane & 15) << 2;
    const int c0 = (w << 4) + ((lane >> 4) << 3);
    const bool active = (w << 4) < N;

    ull acc[4][4];
#pragma unroll
    for (int r = 0; r < 4; r++)
#pragma unroll
        for (int cp = 0; cp < 4; cp++) acc[r][cp] = 0ull;

    float wpf[8];
#pragma unroll
    for (int t = 0; t < 8; t++) {
        int e = tid + (t << 8); int kk = e >> 7, j = e & 127;
        wpf[t] = (kk < K && j < N) ? W[kk * N + j] : 0.f;
    }

    for (int ch = 0; ch < NC; ch++) {
        float* B = Bs + ((ch & 1) << 11);
#pragma unroll
        for (int t = 0; t < 8; t++) B[tid + (t << 8)] = wpf[t];
        __syncthreads();
        if (ch + 1 < NC) {
            int kb = (ch + 1) << 4;
#pragma unroll
            for (int t = 0; t < 8; t++) {
                int e = tid + (t << 8); int kk = kb + (e >> 7), j = e & 127;
                wpf[t] = (kk < K && j < N) ? W[kk * N + j] : 0.f;
            }
        }
        if (active) {
            const float* Ak = A + (ch << 4) * TM + r0;
            const float* Bk = B + c0;
#pragma unroll
            for (int kk = 0; kk < 16; kk++) {
                float4 a4 = *(const float4*)(Ak + (kk << 6));
                ulonglong2 b01 = *(const ulonglong2*)(Bk + (kk << 7));
                ulonglong2 b23 = *(const ulonglong2*)(Bk + (kk << 7) + 4);
                ull ar[4] = { pack2(a4.x, a4.x), pack2(a4.y, a4.y),
                              pack2(a4.z, a4.z), pack2(a4.w, a4.w) };
                ull bp[4] = { b01.x, b01.y, b23.x, b23.y };
#pragma unroll
                for (int r = 0; r < 4; r++)
#pragma unroll
                    for (int cp = 0; cp < 4; cp++)
                        acc[r][cp] = fma2(ar[r], bp[cp], acc[r][cp]);
            }
        }
    }

    if (active) {
#pragma unroll
        for (int cp = 0; cp < 4; cp++) {
            int c = c0 + (cp << 1);
            float lo, hi;
            if (MODE == 0) {
                float blo = bias[c], bhi = bias[c + 1];
#pragma unroll
                for (int r = 0; r < 4; r++) {
                    unpack2(acc[r][cp], lo, hi);
                    lo += blo; hi += bhi;
                    Out[c * TM + r0 + r]       = lo > 0.f ? lo : 0.01f * lo;
                    Out[(c + 1) * TM + r0 + r] = hi > 0.f ? hi : 0.01f * hi;
                }
            } else if (MODE == 1) {
#pragma unroll
                for (int r = 0; r < 4; r++) {
                    unpack2(acc[r][cp], lo, hi);
                    if (c < N)     Out[c * TM + r0 + r]       = lo + bias[c];
                    if (c + 1 < N) Out[(c + 1) * TM + r0 + r] = hi + bias[c + 1];
                }
            } else {
                float blo = bias[c], bhi = bias[c + 1];
#pragma unroll
                for (int r = 0; r < 4; r++) {
                    if (r0 + r < m) {
                        int uv = s_uv[r0 + r];
                        unpack2(acc[r][cp], lo, hi);
                        uvmap[c * UVE + uv]       = lo + blo;
                        uvmap[(c + 1) * UVE + uv] = hi + bhi;
                    }
                }
            }
        }
    }
    __syncthreads();
}

__global__ __launch_bounds__(256, 2)
void mlp_k(const float* __restrict__ latent_z, const float* __restrict__ latent_f,
           const float* __restrict__ cano_xyz,
           const float* __restrict__ m1_w_in, const float* __restrict__ m1_b_in,
           const float* __restrict__ m1_w_hid, const float* __restrict__ m1_b_hid,
           const float* __restrict__ m1_w_out, const float* __restrict__ m1_b_out,
           const float* __restrict__ m2_w_in, const float* __restrict__ m2_b_in,
           const float* __restrict__ m2_w_hid, const float* __restrict__ m2_b_hid,
           const float* __restrict__ m2_w_out, const float* __restrict__ m2_b_out,
           const int* __restrict__ uv_idx,
           const int* __restrict__ order, const int* __restrict__ offsets,
           float* __restrict__ uvmap)
{
    extern __shared__ float sm[];
    float* Xs = sm;                        // [112][64]
    float* Hp = Xs + 112 * TM;             // [128][64]
    float* Hq = Hp + 128 * TM;             // [128][64]
    float* Bs = Hq + 128 * TM;             // [2][2048]
    int*   s_idx = (int*)(Bs + 4096);      // [64]
    int*   s_uv  = s_idx + TM;             // [64]

    int p = blockIdx.x / NT;
    int t = blockIdx.x % NT;
    int beg = offsets[p], end = offsets[p + 1];
    int start = beg + t * TM;
    if (start >= end) return;
    int m = min(TM, end - start);
    int tid = threadIdx.x;

    if (tid < TM) {
        int rr = tid < m ? tid : (m - 1);
        int gid = order[start + rr];
        s_idx[tid] = gid;
        s_uv[tid] = uv_idx[gid];
    }
    __syncthreads();

    for (int e = tid; e < 112 * TM; e += 256) {
        int d = e >> 6, r = e & 63;
        float v = 0.f;
        if (d < 64)       v = latent_f[p * 64 + d];
        else if (d < 96)  v = latent_z[s_idx[r] * 32 + (d - 64)];
        else if (d < 99)  v = cano_xyz[s_idx[r] * 3 + (d - 96)];
        Xs[e] = v;
    }

    layer2<0>(Xs, 96, 6,  m1_w_in  + p * 96 * 128, 128, m1_b_in  + p * 128, Hp, Bs, tid, 0, 0, m);
    layer2<0>(Hp, 128, 8, m1_w_hid + (p * 2 + 0) * 16384, 128, m1_b_hid + (p * 2 + 0) * 128, Hq, Bs, tid, 0, 0, m);
    layer2<0>(Hq, 128, 8, m1_w_hid + (p * 2 + 1) * 16384, 128, m1_b_hid + (p * 2 + 1) * 128, Hp, Bs, tid, 0, 0, m);
    layer2<1>(Hp, 128, 8, m1_w_out + p * 128 * 11, 11, m1_b_out + p * 11, Xs + 99 * TM, Bs, tid, 0, 0, m);
    layer2<0>(Xs, 110, 7, m2_w_in  + p * 110 * 128, 128, m2_b_in  + p * 128, Hp, Bs, tid, 0, 0, m);
    layer2<0>(Hp, 128, 8, m2_w_hid + (p * 2 + 0) * 16384, 128, m2_b_hid + (p * 2 + 0) * 128, Hq, Bs, tid, 0, 0, m);
    layer2<0>(Hq, 128, 8, m2_w_hid + (p * 2 + 1) * 16384, 128, m2_b_hid + (p * 2 + 1) * 128, Hp, Bs, tid, 0, 0, m);
    layer2<2>(Hp, 128, 8, m2_w_out + p * 128 * 32, 32, m2_b_out + p * 32, (float*)0, Bs, tid, s_uv, uvmap, m);
}

// ---------- CNN ----------
template<bool NORM, bool RELU, int TW>
__device__ __forceinline__ float conv_val(const float* __restrict__ in, int cin,
                                          int x0, int y0, int e, float mn, float is) {
    int row = e / TW, col = e - row * TW;
    int iy = y0 + row - 1, ix = x0 + col - 1;
    float v = 0.f;
    if (iy >= 0 && iy < 256 && ix >= 0 && ix < 256) {
        v = in[cin * UVE + iy * 256 + ix];
        if (NORM) v = (v - mn) * is;
        if (RELU) v = fmaxf(v, 0.f);
    }
    return v;
}

// 16x16 px x 64 co per block. Thread: 2x2 px (pg) x 16 co (cg). f32x2 over px pairs. 2 CTA/SM.
// Weights staged k-major [k9][co64] so one LDS.128 feeds 2 couts (4 fma2).
template<int CIN, bool RELU, bool NORM, bool STATS>
__global__ __launch_bounds__(256, 2)
void conv64_k(const float* __restrict__ in, const float2* __restrict__ wt,
              const float* __restrict__ bias,
              const float* __restrict__ mean, const float* __restrict__ invstd,
              float* __restrict__ out,
              float* __restrict__ psum, float* __restrict__ psumsq)
{
    __shared__ __align__(16) float tA[2][324];
    __shared__ __align__(16) float tB[2][328];
    __shared__ __align__(16) float2 ws[2][576];

    const int bx = blockIdx.x;
    const int x0 = (bx & 15) << 4, y0 = (bx >> 4) << 4;
    const int tid = threadIdx.x;
    const int pg = tid & 63, cg = tid >> 6;
    const int lx = (pg & 7) << 1, ly = (pg >> 3) << 1;

    ull acc[16][2];
#pragma unroll
    for (int co = 0; co < 16; co++) { acc[co][0] = 0ull; acc[co][1] = 0ull; }

    float tv0, tv1 = 0.f;
    float2 wv0, wv1, wv2 = make_float2(0.f, 0.f);
    {
        float mn = NORM ? mean[0] : 0.f, is = NORM ? invstd[0] : 1.f;
        tv0 = conv_val<NORM, RELU, 18>(in, 0, x0, y0, tid, mn, is);
        if (tid < 68) tv1 = conv_val<NORM, RELU, 18>(in, 0, x0, y0, tid + 256, mn, is);
        wv0 = wt[tid]; wv1 = wt[tid + 256];
        if (tid < 64) wv2 = wt[tid + 512];
    }

    for (int cin = 0; cin < CIN; cin++) {
        const int b = cin & 1;
        tA[b][tid] = tv0; tB[b][tid + 1] = tv0;
        if (tid < 68) { tA[b][tid + 256] = tv1; tB[b][tid + 257] = tv1; }
        ws[b][tid] = wv0; ws[b][tid + 256] = wv1;
        if (tid < 64) ws[b][tid + 512] = wv2;
        __syncthreads();
        if (cin + 1 < CIN) {
            int c2 = cin + 1;
            float mn = NORM ? mean[c2] : 0.f, is = NORM ? invstd[c2] : 1.f;
            tv0 = conv_val<NORM, RELU, 18>(in, c2, x0, y0, tid, mn, is);
            if (tid < 68) tv1 = conv_val<NORM, RELU, 18>(in, c2, x0, y0, tid + 256, mn, is);
            const float2* wp = wt + c2 * 576;
            wv0 = wp[tid]; wv1 = wp[tid + 256];
            if (tid < 64) wv2 = wp[tid + 512];
        }
        ull pp[4][3];
#pragma unroll
        for (int r = 0; r < 4; r++) {
            int base = (ly + r) * 18 + lx;
            pp[r][0] = *(const ull*)&tA[b][base];
            pp[r][1] = *(const ull*)&tB[b][base + 2];
            pp[r][2] = *(const ull*)&tA[b][base + 2];
        }
        const float2* wk = ws[b] + (cg << 4);
#pragma unroll
        for (int k = 0; k < 9; k++) {
            const int ky = k / 3, kx = k % 3;
            ull p0 = pp[ky][kx];
            ull p1 = pp[ky + 1][kx];
#pragma unroll
            for (int cop = 0; cop < 8; cop++) {
                ulonglong2 w2 = *(const ulonglong2*)&wk[k * 64 + (cop << 1)];
                acc[(cop << 1)][0]     = fma2(p0, w2.x, acc[(cop << 1)][0]);
                acc[(cop << 1)][1]     = fma2(p1, w2.x, acc[(cop << 1)][1]);
                acc[(cop << 1) + 1][0] = fma2(p0, w2.y, acc[(cop << 1) + 1][0]);
                acc[(cop << 1) + 1][1] = fma2(p1, w2.y, acc[(cop << 1) + 1][1]);
            }
        }
        __syncthreads();
    }

    const int wpar = (tid >> 5) & 1;
#pragma unroll
    for (int co = 0; co < 16; co++) {
        int c = (cg << 4) + co;
        float bb = bias[c];
        float v0, v1, v2, v3;
        unpack2(acc[co][0], v0, v1);
        unpack2(acc[co][1], v2, v3);
        v0 += bb; v1 += bb; v2 += bb; v3 += bb;
        float* op = out + c * UVE + (y0 + ly) * 256 + (x0 + lx);
        *(float2*)op         = make_float2(v0, v1);
        *(float2*)(op + 256) = make_float2(v2, v3);
        if (STATS) {
            float s = v0 + v1 + v2 + v3;
            float q = v0 * v0 + v1 * v1 + v2 * v2 + v3 * v3;
#pragma unroll
            for (int d = 16; d >= 1; d >>= 1) {
                s += __shfl_down_sync(0xffffffffu, s, d);
                q += __shfl_down_sync(0xffffffffu, q, d);
            }
            if ((tid & 31) == 0) {
                psum[c * 512 + (bx << 1) + wpar] = s;
                psumsq[c * 512 + (bx << 1) + wpar] = q;
            }
        }
    }
}

__global__ void finalize_k(const float* __restrict__ psum, const float* __restrict__ psumsq,
                           float* __restrict__ mean, float* __restrict__ invstd) {
    __shared__ float s1[256], s2[256];
    int c = blockIdx.x, tid = threadIdx.x;
    s1[tid] = psum[c * 512 + tid] + psum[c * 512 + 256 + tid];
    s2[tid] = psumsq[c * 512 + tid] + psumsq[c * 512 + 256 + tid];
    __syncthreads();
    for (int s = 128; s > 0; s >>= 1) {
        if (tid < s) { s1[tid] += s1[tid + s]; s2[tid] += s2[tid + s]; }
        __syncthreads();
    }
    if (tid == 0) {
        float mu = s1[0] * (1.f / UVE);
        float var = s2[0] * (1.f / UVE) - mu * mu;
        mean[c] = mu;
        invstd[c] = rsqrtf(var + 1e-5f);
    }
}

// conv_out: 64 -> 3, normalized input, sigmoid. Block 32x16 px; thread = 1 px pair x 3 couts.
__global__ __launch_bounds__(256, 2)
void convout_k(const float* __restrict__ in, const float2* __restrict__ wt,
               const float* __restrict__ bias,
               const float* __restrict__ mean, const float* __restrict__ invstd,
               float* __restrict__ out)
{
    __shared__ __align__(16) float tA[2][612];
    __shared__ __align__(16) float tB[2][616];
    __shared__ __align__(16) float2 wds[1728];

    const int bx = blockIdx.x;
    const int x0 = (bx & 7) << 5, y0 = (bx >> 3) << 4;
    const int tid = threadIdx.x;
    const int lx = (tid & 15) << 1, ly = tid >> 4;

    for (int e = tid; e < 1728; e += 256) wds[e] = wt[e];

    ull acc0 = 0ull, acc1 = 0ull, acc2 = 0ull;

    float tv0, tv1 = 0.f, tv2 = 0.f;
    {
        float mn = mean[0], is = invstd[0];
        tv0 = conv_val<true, false, 34>(in, 0, x0, y0, tid, mn, is);
        tv1 = conv_val<true, false, 34>(in, 0, x0, y0, tid + 256, mn, is);
        if (tid < 100) tv2 = conv_val<true, false, 34>(in, 0, x0, y0, tid + 512, mn, is);
    }

    for (int cin = 0; cin < 64; cin++) {
        const int b = cin & 1;
        tA[b][tid] = tv0; tB[b][tid + 1] = tv0;
        tA[b][tid + 256] = tv1; tB[b][tid + 257] = tv1;
        if (tid < 100) { tA[b][tid + 512] = tv2; tB[b][tid + 513] = tv2; }
        __syncthreads();
        if (cin + 1 < 64) {
            int c2 = cin + 1;
            float mn = mean[c2], is = invstd[c2];
            tv0 = conv_val<true, false, 34>(in, c2, x0, y0, tid, mn, is);
            tv1 = conv_val<true, false, 34>(in, c2, x0, y0, tid + 256, mn, is);
            if (tid < 100) tv2 = conv_val<true, false, 34>(in, c2, x0, y0, tid + 512, mn, is);
        }
        ull pp[3][3];
#pragma unroll
        for (int r = 0; r < 3; r++) {
            int base = (ly + r) * 34 + lx;
            pp[r][0] = *(const ull*)&tA[b][base];
            pp[r][1] = *(const ull*)&tB[b][base + 2];
            pp[r][2] = *(const ull*)&tA[b][base + 2];
        }
        const float2* wc = wds + cin * 27;
#pragma unroll
        for (int r = 0; r < 3; r++)
#pragma unroll
            for (int kx = 0; kx < 3; kx++) {
                acc0 = fma2(pp[r][kx], *(const ull*)&wc[r * 3 + kx],      acc0);
                acc1 = fma2(pp[r][kx], *(const ull*)&wc[9 + r * 3 + kx],  acc1);
                acc2 = fma2(pp[r][kx], *(const ull*)&wc[18 + r * 3 + kx], acc2);
            }
        __syncthreads();
    }

    int o = (y0 + ly) * 256 + x0 + lx;
    float lo, hi;
    unpack2(acc0, lo, hi);
    *(float2*)(out + o) = make_float2(1.f / (1.f + __expf(-(lo + bias[0]))),
                                      1.f / (1.f + __expf(-(hi + bias[0]))));
    unpack2(acc1, lo, hi);
    *(float2*)(out + UVE + o) = make_float2(1.f / (1.f + __expf(-(lo + bias[1]))),
                                            1.f / (1.f + __expf(-(hi + bias[1]))));
    unpack2(acc2, lo, hi);
    *(float2*)(out + 2 * UVE + o) = make_float2(1.f / (1.f + __expf(-(lo + bias[2]))),
                                                1.f / (1.f + __expf(-(hi + bias[2]))));
}

// ---------- launch ----------
extern "C" void kernel_launch(void* const* d_in, const int* in_sizes, int n_in,
                              void* d_out, int out_size)
{
    const float* latent_z  = (const float*)d_in[0];
    const float* latent_f  = (const float*)d_in[1];
    const float* cano_xyz  = (const float*)d_in[2];
    const float* m1_w_in   = (const float*)d_in[3];
    const float* m1_b_in   = (const float*)d_in[4];
    const float* m1_w_hid  = (const float*)d_in[5];
    const float* m1_b_hid  = (const float*)d_in[6];
    const float* m1_w_out  = (const float*)d_in[7];
    const float* m1_b_out  = (const float*)d_in[8];
    const float* m2_w_in   = (const float*)d_in[9];
    const float* m2_b_in   = (const float*)d_in[10];
    const float* m2_w_hid  = (const float*)d_in[11];
    const float* m2_b_hid  = (const float*)d_in[12];
    const float* m2_w_out  = (const float*)d_in[13];
    const float* m2_b_out  = (const float*)d_in[14];
    const float* conv_in_w = (const float*)d_in[15];
    const float* conv_in_b = (const float*)d_in[16];
    const float* conv_hid_w= (const float*)d_in[17];
    const float* conv_hid_b= (const float*)d_in[18];
    const float* conv_out_w= (const float*)d_in[19];
    const float* conv_out_b= (const float*)d_in[20];
    const int*   gs_part   = (const int*)d_in[21];
    const int*   uv_idx    = (const int*)d_in[22];
    float* outp = (float*)d_out;

    void *p_counts, *p_offsets, *p_cursor, *p_order, *p_uvmap, *p_bufA, *p_bufB;
    void *p_mean, *p_invstd, *p_wt, *p_ps, *p_pq;
    cudaGetSymbolAddress(&p_counts, g_counts);
    cudaGetSymbolAddress(&p_offsets, g_offsets);
    cudaGetSymbolAddress(&p_cursor, g_cursor);
    cudaGetSymbolAddress(&p_order, g_order);
    cudaGetSymbolAddress(&p_uvmap, g_uvmap);
    cudaGetSymbolAddress(&p_bufA, g_bufA);
    cudaGetSymbolAddress(&p_bufB, g_bufB);
    cudaGetSymbolAddress(&p_mean, g_mean);
    cudaGetSymbolAddress(&p_invstd, g_invstd);
    cudaGetSymbolAddress(&p_wt, g_wt);
    cudaGetSymbolAddress(&p_ps, g_psum);
    cudaGetSymbolAddress(&p_pq, g_psumsq);

    cudaMemsetAsync(p_counts, 0, 8 * sizeof(int), 0);
    cudaMemsetAsync(p_uvmap, 0, 32 * UVE * sizeof(float), 0);

    wprep_k<<<432, 256>>>(conv_in_w, conv_hid_w, conv_out_w, (float2*)p_wt);

    int gb = (GN + 255) / 256;
    count_k<<<gb, 256>>>(gs_part, (int*)p_counts);
    scan_k<<<1, 32>>>((const int*)p_counts, (int*)p_offsets, (int*)p_cursor);
    scatter_k<<<gb, 256>>>(gs_part, (int*)p_cursor, (int*)p_order);

    static bool attr_set = false;
    if (!attr_set) {
        cudaFuncSetAttribute(mlp_k, cudaFuncAttributeMaxDynamicSharedMemorySize, 111104);
        attr_set = true;
    }
    mlp_k<<<PN * NT, 256, 111104>>>(
        latent_z, latent_f, cano_xyz,
        m1_w_in, m1_b_in, m1_w_hid, m1_b_hid, m1_w_out, m1_b_out,
        m2_w_in, m2_b_in, m2_w_hid, m2_b_hid, m2_w_out, m2_b_out,
        uv_idx, (const int*)p_order, (const int*)p_offsets, (float*)p_uvmap);

    float* bufA = (float*)p_bufA;
    float* bufB = (float*)p_bufB;
    float* mean = (float*)p_mean;
    float* invstd = (float*)p_invstd;
    float* ps = (float*)p_ps;
    float* pq = (float*)p_pq;
    const float2* wt = (const float2*)p_wt;

    conv64_k<32, false, false, false><<<256, 256>>>((const float*)p_uvmap, wt, conv_in_b, 0, 0, bufA, 0, 0);
    conv64_k<64, true, false, true><<<256, 256>>>(bufA, wt + 18432, conv_hid_b, 0, 0, bufB, ps, pq);
    finalize_k<<<64, 256>>>(ps, pq, mean, invstd);
    conv64_k<64, true, true, true><<<256, 256>>>(bufB, wt + 18432 + 36864, conv_hid_b + 64, mean, invstd, bufA, ps, pq);
    finalize_k<<<64, 256>>>(ps, pq, mean, invstd);
    conv64_k<64, true, true, true><<<256, 256>>>(bufA, wt + 18432 + 2 * 36864, conv_hid_b + 128, mean, invstd, bufB, ps, pq);
    finalize_k<<<64, 256>>>(ps, pq, mean, invstd);
    convout_k<<<128, 256>>>(bufB, wt + 129024, conv_out_b, mean, invstd, outp);
}

// round 10
// speedup vs baseline: 1.1781x; 1.0336x over previous
#include <cuda_runtime.h>
#include <math.h>

typedef unsigned long long ull;

#define GN 40000
#define PN 5
#define UVE 65536
#define TM 64
#define NT 625   // ceil(GN/TM)

__device__ __forceinline__ ull fma2(ull a, ull b, ull c) {
    ull d; asm("fma.rn.f32x2 %0, %1, %2, %3;" : "=l"(d) : "l"(a), "l"(b), "l"(c)); return d;
}
__device__ __forceinline__ ull pack2(float lo, float hi) {
    ull d; asm("mov.b64 %0, {%1, %2};" : "=l"(d) : "f"(lo), "f"(hi)); return d;
}
__device__ __forceinline__ void unpack2(ull v, float& lo, float& hi) {
    asm("mov.b64 {%0, %1}, %2;" : "=f"(lo), "=f"(hi) : "l"(v));
}

// ---------- scratch ----------
__device__ int    g_counts[8];
__device__ int    g_offsets[8];
__device__ int    g_cursor[8];
__device__ int    g_order[GN];
__device__ float  g_uvmap[32 * UVE];
__device__ float  g_bufA[64 * UVE];
__device__ float  g_bufB[64 * UVE];
__device__ float  g_mean[64];
__device__ float  g_invstd[64];
__device__ float  g_psum[64 * 512];
__device__ float  g_psumsq[64 * 512];
__device__ float  g_wtf[129024];  // k-major floats: in[cin32][k9][co64]@0 ; hid[l][cin64][k9][co64]@18432
__device__ float2 g_wt[1728];     // convout dup: [cin64][co3][9]

// ---------- bucketing (3-kernel, measured-good) ----------
__global__ void count_k(const int* __restrict__ part, int* counts) {
    int g = blockIdx.x * blockDim.x + threadIdx.x;
    if (g < GN) atomicAdd(&counts[part[g]], 1);
}
__global__ void scan_k(const int* __restrict__ counts, int* offsets, int* cursor) {
    if (threadIdx.x == 0) {
        int s = 0;
        for (int p = 0; p < PN; p++) { offsets[p] = s; cursor[p] = s; s += counts[p]; }
        offsets[PN] = s;
    }
}
__global__ void scatter_k(const int* __restrict__ part, int* cursor, int* __restrict__ order) {
    int g = blockIdx.x * blockDim.x + threadIdx.x;
    if (g < GN) { int pos = atomicAdd(&cursor[part[g]], 1); order[pos] = g; }
}

// ---------- conv weight transpose ----------
__global__ void wprep_k(const float* __restrict__ win, const float* __restrict__ whid,
                        const float* __restrict__ wout, float* __restrict__ wtf,
                        float2* __restrict__ wt) {
    int i = blockIdx.x * 256 + threadIdx.x;
    if (i < 18432) {              // [cin32][k9][co64] <- OIHW [64][32][9]
        int k = i % 9; int t = i / 9; int co = t % 64, cin = t / 64;
        wtf[cin * 576 + k * 64 + co] = win[(co * 32 + cin) * 9 + k];
    }
    if (i < 110592) {             // [l][cin64][k9][co64] <- [l][64][64][9]
        int k = i % 9; int t = i / 9; int co = t % 64;
        int t2 = t / 64; int cin = t2 % 64, l = t2 / 64;
        wtf[18432 + l * 36864 + cin * 576 + k * 64 + co] = whid[((l * 64 + co) * 64 + cin) * 9 + k];
    }
    if (i < 1728) {               // convout dup co-major: [cin64][co3][9] <- [3][64][9]
        int k = i % 9; int t = i / 9; int co = t % 3, cin = t / 3;
        float v = wout[(co * 64 + cin) * 9 + k];
        wt[i] = make_float2(v, v);
    }
}

// ---------- fused MLP (TM=64, col-packed f32x2, double-buffered weights) ----------
template<int MODE>  // 0: lrelu->Out  1: masked cols->Out
__device__ __forceinline__ void layer2(
    const float* A, int K, int NC,
    const float* __restrict__ W, int N, const float* __restrict__ bias,
    float* Out, float* Bs, int tid)
{
    const int w = tid >> 5, lane = tid & 31;
    const int r0 = (lane & 15) << 2;
    const int c0 = (w << 4) + ((lane >> 4) << 3);
    const bool active = (w << 4) < N;

    ull acc[4][4];
#pragma unroll
    for (int r = 0; r < 4; r++)
#pragma unroll
        for (int cp = 0; cp < 4; cp++) acc[r][cp] = 0ull;

    float wpf[8];
#pragma unroll
    for (int t = 0; t < 8; t++) {
        int e = tid + (t << 8); int kk = e >> 7, j = e & 127;
        wpf[t] = (kk < K && j < N) ? W[kk * N + j] : 0.f;
    }

    for (int ch = 0; ch < NC; ch++) {
        float* B = Bs + ((ch & 1) << 11);
#pragma unroll
        for (int t = 0; t < 8; t++) B[tid + (t << 8)] = wpf[t];
        __syncthreads();
        if (ch + 1 < NC) {
            int kb = (ch + 1) << 4;
#pragma unroll
            for (int t = 0; t < 8; t++) {
                int e = tid + (t << 8); int kk = kb + (e >> 7), j = e & 127;
                wpf[t] = (kk < K && j < N) ? W[kk * N + j] : 0.f;
            }
        }
        if (active) {
            const float* Ak = A + (ch << 4) * TM + r0;
            const float* Bk = B + c0;
#pragma unroll
            for (int kk = 0; kk < 16; kk++) {
                float4 a4 = *(const float4*)(Ak + (kk << 6));
                ulonglong2 b01 = *(const ulonglong2*)(Bk + (kk << 7));
                ulonglong2 b23 = *(const ulonglong2*)(Bk + (kk << 7) + 4);
                ull ar[4] = { pack2(a4.x, a4.x), pack2(a4.y, a4.y),
                              pack2(a4.z, a4.z), pack2(a4.w, a4.w) };
                ull bp[4] = { b01.x, b01.y, b23.x, b23.y };
#pragma unroll
                for (int r = 0; r < 4; r++)
#pragma unroll
                    for (int cp = 0; cp < 4; cp++)
                        acc[r][cp] = fma2(ar[r], bp[cp], acc[r][cp]);
            }
        }
    }

    if (active) {
#pragma unroll
        for (int cp = 0; cp < 4; cp++) {
            int c = c0 + (cp << 1);
            float lo, hi;
            if (MODE == 0) {
                float blo = bias[c], bhi = bias[c + 1];
#pragma unroll
                for (int r = 0; r < 4; r++) {
                    unpack2(acc[r][cp], lo, hi);
                    lo += blo; hi += bhi;
                    Out[c * TM + r0 + r]       = lo > 0.f ? lo : 0.01f * lo;
                    Out[(c + 1) * TM + r0 + r] = hi > 0.f ? hi : 0.01f * hi;
                }
            } else {
#pragma unroll
                for (int r = 0; r < 4; r++) {
                    unpack2(acc[r][cp], lo, hi);
                    if (c < N)     Out[c * TM + r0 + r]       = lo + bias[c];
                    if (c + 1 < N) Out[(c + 1) * TM + r0 + r] = hi + bias[c + 1];
                }
            }
        }
    }
    __syncthreads();
}

// Row-spread output layer (small N): all 8 warps active; warp w owns rows [8w,8w+8).
// lane = (row_local<<2) | cg4 ; thread handles cols {cg4 + 4j}.
template<int NJ, bool SCATTER>
__device__ __forceinline__ void layer_rs(
    const float* A, int K, int NC,
    const float* __restrict__ W, int N, const float* __restrict__ bias,
    float* Out, float* Bs, int tid,
    const int* s_uv, float* uvmap, int m)
{
    const int w = tid >> 5, lane = tid & 31;
    const int r = (w << 3) + (lane >> 2);
    const int cg4 = lane & 3;

    float acc[NJ];
#pragma unroll
    for (int j = 0; j < NJ; j++) acc[j] = 0.f;

    float wpf[8];
#pragma unroll
    for (int t = 0; t < 8; t++) {
        int e = tid + (t << 8); int kk = e >> 7, j = e & 127;
        wpf[t] = (kk < K && j < N) ? W[kk * N + j] : 0.f;
    }

    for (int ch = 0; ch < NC; ch++) {
        float* B = Bs + ((ch & 1) << 11);
#pragma unroll
        for (int t = 0; t < 8; t++) B[tid + (t << 8)] = wpf[t];
        __syncthreads();
        if (ch + 1 < NC) {
            int kb = (ch + 1) << 4;
#pragma unroll
            for (int t = 0; t < 8; t++) {
                int e = tid + (t << 8); int kk = kb + (e >> 7), j = e & 127;
                wpf[t] = (kk < K && j < N) ? W[kk * N + j] : 0.f;
            }
        }
        const float* Ak = A + (ch << 4) * TM + r;
#pragma unroll
        for (int kk = 0; kk < 16; kk++) {
            float a = Ak[kk << 6];
            const float* Bk = B + (kk << 7) + cg4;
#pragma unroll
            for (int j = 0; j < NJ; j++)
                acc[j] += a * Bk[j << 2];
        }
    }

    if (!SCATTER) {
#pragma unroll
        for (int j = 0; j < NJ; j++) {
            int c = cg4 + (j << 2);
            if (c < N) Out[c * TM + r] = acc[j] + bias[c];
        }
    } else {
        if (r < m) {
            int uv = s_uv[r];
#pragma unroll
            for (int j = 0; j < NJ; j++) {
                int c = cg4 + (j << 2);
                if (c < N) uvmap[c * UVE + uv] = acc[j] + bias[c];
            }
        }
    }
    __syncthreads();
}

__global__ __launch_bounds__(256, 2)
void mlp_k(const float* __restrict__ latent_z, const float* __restrict__ latent_f,
           const float* __restrict__ cano_xyz,
           const float* __restrict__ m1_w_in, const float* __restrict__ m1_b_in,
           const float* __restrict__ m1_w_hid, const float* __restrict__ m1_b_hid,
           const float* __restrict__ m1_w_out, const float* __restrict__ m1_b_out,
           const float* __restrict__ m2_w_in, const float* __restrict__ m2_b_in,
           const float* __restrict__ m2_w_hid, const float* __restrict__ m2_b_hid,
           const float* __restrict__ m2_w_out, const float* __restrict__ m2_b_out,
           const int* __restrict__ uv_idx,
           const int* __restrict__ order, const int* __restrict__ offsets,
           float* __restrict__ uvmap)
{
    extern __shared__ float sm[];
    float* Xs = sm;                        // [112][64]
    float* Hp = Xs + 112 * TM;             // [128][64]
    float* Hq = Hp + 128 * TM;             // [128][64]
    float* Bs = Hq + 128 * TM;             // [2][2048]
    int*   s_idx = (int*)(Bs + 4096);      // [64]
    int*   s_uv  = s_idx + TM;             // [64]

    int p = blockIdx.x / NT;
    int t = blockIdx.x % NT;
    int beg = offsets[p], end = offsets[p + 1];
    int start = beg + t * TM;
    if (start >= end) return;
    int m = min(TM, end - start);
    int tid = threadIdx.x;

    if (tid < TM) {
        int rr = tid < m ? tid : (m - 1);
        int gid = order[start + rr];
        s_idx[tid] = gid;
        s_uv[tid] = uv_idx[gid];
    }
    __syncthreads();

    for (int e = tid; e < 112 * TM; e += 256) {
        int d = e >> 6, r = e & 63;
        float v = 0.f;
        if (d < 64)       v = latent_f[p * 64 + d];
        else if (d < 96)  v = latent_z[s_idx[r] * 32 + (d - 64)];
        else if (d < 99)  v = cano_xyz[s_idx[r] * 3 + (d - 96)];
        Xs[e] = v;
    }

    layer2<0>(Xs, 96, 6,  m1_w_in  + p * 96 * 128, 128, m1_b_in  + p * 128, Hp, Bs, tid);
    layer2<0>(Hp, 128, 8, m1_w_hid + (p * 2 + 0) * 16384, 128, m1_b_hid + (p * 2 + 0) * 128, Hq, Bs, tid);
    layer2<0>(Hq, 128, 8, m1_w_hid + (p * 2 + 1) * 16384, 128, m1_b_hid + (p * 2 + 1) * 128, Hp, Bs, tid);
    layer_rs<3, false>(Hp, 128, 8, m1_w_out + p * 128 * 11, 11, m1_b_out + p * 11, Xs + 99 * TM, Bs, tid, 0, 0, m);
    layer2<0>(Xs, 110, 7, m2_w_in  + p * 110 * 128, 128, m2_b_in  + p * 128, Hp, Bs, tid);
    layer2<0>(Hp, 128, 8, m2_w_hid + (p * 2 + 0) * 16384, 128, m2_b_hid + (p * 2 + 0) * 128, Hq, Bs, tid);
    layer2<0>(Hq, 128, 8, m2_w_hid + (p * 2 + 1) * 16384, 128, m2_b_hid + (p * 2 + 1) * 128, Hp, Bs, tid);
    layer_rs<8, true>(Hp, 128, 8, m2_w_out + p * 128 * 32, 32, m2_b_out + p * 32, (float*)0, Bs, tid, s_uv, uvmap, m);
}

// ---------- CNN ----------
template<bool NORM, bool RELU, int TW>
__device__ __forceinline__ float conv_val(const float* __restrict__ in, int cin,
                                          int x0, int y0, int e, float mn, float is) {
    int row = e / TW, col = e - row * TW;
    int iy = y0 + row - 1, ix = x0 + col - 1;
    float v = 0.f;
    if (iy >= 0 && iy < 256 && ix >= 0 && ix < 256) {
        v = in[cin * UVE + iy * 256 + ix];
        if (NORM) v = (v - mn) * is;
        if (RELU) v = fmaxf(v, 0.f);
    }
    return v;
}

// 16x16 px x 64 co per block. Thread: 2x2 px (pg) x 16 co (cg). f32x2 packed over COUT pairs:
// weights un-duplicated k-major (pair = contiguous LDS), pixels duplicated {v,v} in tile.
// Single barrier per cin (double-buffered; trailing sync provably redundant).
template<int CIN, bool RELU, bool NORM, bool STATS>
__global__ __launch_bounds__(256, 2)
void conv64_k(const float* __restrict__ in, const float* __restrict__ wtf,
              const float* __restrict__ bias,
              const float* __restrict__ mean, const float* __restrict__ invstd,
              float* __restrict__ out,
              float* __restrict__ psum, float* __restrict__ psumsq)
{
    __shared__ __align__(16) ull   tD[2][324];
    __shared__ __align__(16) float wsf[2][576];

    const int bx = blockIdx.x;
    const int x0 = (bx & 15) << 4, y0 = (bx >> 4) << 4;
    const int tid = threadIdx.x;
    const int pg = tid & 63, cg = tid >> 6;
    const int lx = (pg & 7) << 1, ly = (pg >> 3) << 1;

    ull acc[8][4];   // [copair][q = dy*2+dx]
#pragma unroll
    for (int cp = 0; cp < 8; cp++)
#pragma unroll
        for (int q = 0; q < 4; q++) acc[cp][q] = 0ull;

    float tv0, tv1 = 0.f;
    float wv0, wv1, wv2 = 0.f;
    {
        float mn = NORM ? mean[0] : 0.f, is = NORM ? invstd[0] : 1.f;
        tv0 = conv_val<NORM, RELU, 18>(in, 0, x0, y0, tid, mn, is);
        if (tid < 68) tv1 = conv_val<NORM, RELU, 18>(in, 0, x0, y0, tid + 256, mn, is);
        wv0 = wtf[tid]; wv1 = wtf[tid + 256];
        if (tid < 64) wv2 = wtf[tid + 512];
    }

    for (int cin = 0; cin < CIN; cin++) {
        const int b = cin & 1;
        tD[b][tid] = pack2(tv0, tv0);
        if (tid < 68) tD[b][tid + 256] = pack2(tv1, tv1);
        wsf[b][tid] = wv0; wsf[b][tid + 256] = wv1;
        if (tid < 64) wsf[b][tid + 512] = wv2;
        __syncthreads();
        if (cin + 1 < CIN) {
            int c2 = cin + 1;
            float mn = NORM ? mean[c2] : 0.f, is = NORM ? invstd[c2] : 1.f;
            tv0 = conv_val<NORM, RELU, 18>(in, c2, x0, y0, tid, mn, is);
            if (tid < 68) tv1 = conv_val<NORM, RELU, 18>(in, c2, x0, y0, tid + 256, mn, is);
            const float* wp = wtf + c2 * 576;
            wv0 = wp[tid]; wv1 = wp[tid + 256];
            if (tid < 64) wv2 = wp[tid + 512];
        }
        const ull* td = tD[b];
        const float* wk = wsf[b] + (cg << 4);
#pragma unroll
        for (int ky = 0; ky < 3; ky++) {
            ulonglong2 ra0 = *(const ulonglong2*)&td[(ly + ky) * 18 + lx];
            ulonglong2 ra1 = *(const ulonglong2*)&td[(ly + ky) * 18 + lx + 2];
            ulonglong2 rb0 = *(const ulonglong2*)&td[(ly + ky + 1) * 18 + lx];
            ulonglong2 rb1 = *(const ulonglong2*)&td[(ly + ky + 1) * 18 + lx + 2];
            ull pa[4] = { ra0.x, ra0.y, ra1.x, ra1.y };
            ull pb[4] = { rb0.x, rb0.y, rb1.x, rb1.y };
#pragma unroll
            for (int kx = 0; kx < 3; kx++) {
#pragma unroll
                for (int cp2 = 0; cp2 < 4; cp2++) {
                    ulonglong2 w2 = *(const ulonglong2*)&wk[(ky * 3 + kx) * 64 + (cp2 << 2)];
                    int ce = cp2 << 1;
                    acc[ce][0]     = fma2(pa[kx],     w2.x, acc[ce][0]);
                    acc[ce][1]     = fma2(pa[kx + 1], w2.x, acc[ce][1]);
                    acc[ce][2]     = fma2(pb[kx],     w2.x, acc[ce][2]);
                    acc[ce][3]     = fma2(pb[kx + 1], w2.x, acc[ce][3]);
                    acc[ce + 1][0] = fma2(pa[kx],     w2.y, acc[ce + 1][0]);
                    acc[ce + 1][1] = fma2(pa[kx + 1], w2.y, acc[ce + 1][1]);
                    acc[ce + 1][2] = fma2(pb[kx],     w2.y, acc[ce + 1][2]);
                    acc[ce + 1][3] = fma2(pb[kx + 1], w2.y, acc[ce + 1][3]);
                }
            }
        }
        // no trailing barrier: stage(i+2) is only reachable after sync(i+1),
        // which every warp reaches only after finishing compute(i).
    }

    const int wpar = (tid >> 5) & 1;
#pragma unroll
    for (int cp = 0; cp < 8; cp++) {
        int cA = (cg << 4) + (cp << 1), cB = cA + 1;
        float bA = bias[cA], bB = bias[cB];
        float vA[4], vB[4];
#pragma unroll
        for (int q = 0; q < 4; q++) {
            unpack2(acc[cp][q], vA[q], vB[q]);
            vA[q] += bA; vB[q] += bB;
        }
        float* opA = out + cA * UVE + (y0 + ly) * 256 + (x0 + lx);
        float* opB = out + cB * UVE + (y0 + ly) * 256 + (x0 + lx);
        *(float2*)opA         = make_float2(vA[0], vA[1]);
        *(float2*)(opA + 256) = make_float2(vA[2], vA[3]);
        *(float2*)opB         = make_float2(vB[0], vB[1]);
        *(float2*)(opB + 256) = make_float2(vB[2], vB[3]);
        if (STATS) {
            float sA = vA[0] + vA[1] + vA[2] + vA[3];
            float qA = vA[0] * vA[0] + vA[1] * vA[1] + vA[2] * vA[2] + vA[3] * vA[3];
            float sB = vB[0] + vB[1] + vB[2] + vB[3];
            float qB = vB[0] * vB[0] + vB[1] * vB[1] + vB[2] * vB[2] + vB[3] * vB[3];
#pragma unroll
            for (int d = 16; d >= 1; d >>= 1) {
                sA += __shfl_down_sync(0xffffffffu, sA, d);
                qA += __shfl_down_sync(0xffffffffu, qA, d);
                sB += __shfl_down_sync(0xffffffffu, sB, d);
                qB += __shfl_down_sync(0xffffffffu, qB, d);
            }
            if ((tid & 31) == 0) {
                psum[cA * 512 + (bx << 1) + wpar] = sA;
                psumsq[cA * 512 + (bx << 1) + wpar] = qA;
                psum[cB * 512 + (bx << 1) + wpar] = sB;
                psumsq[cB * 512 + (bx << 1) + wpar] = qB;
            }
        }
    }
}

__global__ void finalize_k(const float* __restrict__ psum, const float* __restrict__ psumsq,
                           float* __restrict__ mean, float* __restrict__ invstd) {
    __shared__ float s1[256], s2[256];
    int c = blockIdx.x, tid = threadIdx.x;
    s1[tid] = psum[c * 512 + tid] + psum[c * 512 + 256 + tid];
    s2[tid] = psumsq[c * 512 + tid] + psumsq[c * 512 + 256 + tid];
    __syncthreads();
    for (int s = 128; s > 0; s >>= 1) {
        if (tid < s) { s1[tid] += s1[tid + s]; s2[tid] += s2[tid + s]; }
        __syncthreads();
    }
    if (tid == 0) {
        float mu = s1[0] * (1.f / UVE);
        float var = s2[0] * (1.f / UVE) - mu * mu;
        mean[c] = mu;
        invstd[c] = rsqrtf(var + 1e-5f);
    }
}

// conv_out: 64 -> 3, normalized input, sigmoid. Block 32x16 px; thread = 1 px pair x 3 couts.
__global__ __launch_bounds__(256, 2)
void convout_k(const float* __restrict__ in, const float2* __restrict__ wt,
               const float* __restrict__ bias,
               const float* __restrict__ mean, const float* __restrict__ invstd,
               float* __restrict__ out)
{
    __shared__ __align__(16) float tA[2][612];
    __shared__ __align__(16) float tB[2][616];
    __shared__ __align__(16) float2 wds[1728];

    const int bx = blockIdx.x;
    const int x0 = (bx & 7) << 5, y0 = (bx >> 3) << 4;
    const int tid = threadIdx.x;
    const int lx = (tid & 15) << 1, ly = tid >> 4;

    for (int e = tid; e < 1728; e += 256) wds[e] = wt[e];

    ull acc0 = 0ull, acc1 = 0ull, acc2 = 0ull;

    float tv0, tv1 = 0.f, tv2 = 0.f;
    {
        float mn = mean[0], is = invstd[0];
        tv0 = conv_val<true, false, 34>(in, 0, x0, y0, tid, mn, is);
        tv1 = conv_val<true, false, 34>(in, 0, x0, y0, tid + 256, mn, is);
        if (tid < 100) tv2 = conv_val<true, false, 34>(in, 0, x0, y0, tid + 512, mn, is);
    }

    for (int cin = 0; cin < 64; cin++) {
        const int b = cin & 1;
        tA[b][tid] = tv0; tB[b][tid + 1] = tv0;
        tA[b][tid + 256] = tv1; tB[b][tid + 257] = tv1;
        if (tid < 100) { tA[b][tid + 512] = tv2; tB[b][tid + 513] = tv2; }
        __syncthreads();
        if (cin + 1 < 64) {
            int c2 = cin + 1;
            float mn = mean[c2], is = invstd[c2];
            tv0 = conv_val<true, false, 34>(in, c2, x0, y0, tid, mn, is);
            tv1 = conv_val<true, false, 34>(in, c2, x0, y0, tid + 256, mn, is);
            if (tid < 100) tv2 = conv_val<true, false, 34>(in, c2, x0, y0, tid + 512, mn, is);
        }
        ull pp[3][3];
#pragma unroll
        for (int r = 0; r < 3; r++) {
            int base = (ly + r) * 34 + lx;
            pp[r][0] = *(const ull*)&tA[b][base];
            pp[r][1] = *(const ull*)&tB[b][base + 2];
            pp[r][2] = *(const ull*)&tA[b][base + 2];
        }
        const float2* wc = wds + cin * 27;
#pragma unroll
        for (int r = 0; r < 3; r++)
#pragma unroll
            for (int kx = 0; kx < 3; kx++) {
                acc0 = fma2(pp[r][kx], *(const ull*)&wc[r * 3 + kx],      acc0);
                acc1 = fma2(pp[r][kx], *(const ull*)&wc[9 + r * 3 + kx],  acc1);
                acc2 = fma2(pp[r][kx], *(const ull*)&wc[18 + r * 3 + kx], acc2);
            }
        __syncthreads();
    }

    int o = (y0 + ly) * 256 + x0 + lx;
    float lo, hi;
    unpack2(acc0, lo, hi);
    *(float2*)(out + o) = make_float2(1.f / (1.f + __expf(-(lo + bias[0]))),
                                      1.f / (1.f + __expf(-(hi + bias[0]))));
    unpack2(acc1, lo, hi);
    *(float2*)(out + UVE + o) = make_float2(1.f / (1.f + __expf(-(lo + bias[1]))),
                                            1.f / (1.f + __expf(-(hi + bias[1]))));
    unpack2(acc2, lo, hi);
    *(float2*)(out + 2 * UVE + o) = make_float2(1.f / (1.f + __expf(-(lo + bias[2]))),
                                                1.f / (1.f + __expf(-(hi + bias[2]))));
}

// ---------- launch ----------
extern "C" void kernel_launch(void* const* d_in, const int* in_sizes, int n_in,
                              void* d_out, int out_size)
{
    const float* latent_z  = (const float*)d_in[0];
    const float* latent_f  = (const float*)d_in[1];
    const float* cano_xyz  = (const float*)d_in[2];
    const float* m1_w_in   = (const float*)d_in[3];
    const float* m1_b_in   = (const float*)d_in[4];
    const float* m1_w_hid  = (const float*)d_in[5];
    const float* m1_b_hid  = (const float*)d_in[6];
    const float* m1_w_out  = (const float*)d_in[7];
    const float* m1_b_out  = (const float*)d_in[8];
    const float* m2_w_in   = (const float*)d_in[9];
    const float* m2_b_in   = (const float*)d_in[10];
    const float* m2_w_hid  = (const float*)d_in[11];
    const float* m2_b_hid  = (const float*)d_in[12];
    const float* m2_w_out  = (const float*)d_in[13];
    const float* m2_b_out  = (const float*)d_in[14];
    const float* conv_in_w = (const float*)d_in[15];
    const float* conv_in_b = (const float*)d_in[16];
    const float* conv_hid_w= (const float*)d_in[17];
    const float* conv_hid_b= (const float*)d_in[18];
    const float* conv_out_w= (const float*)d_in[19];
    const float* conv_out_b= (const float*)d_in[20];
    const int*   gs_part   = (const int*)d_in[21];
    const int*   uv_idx    = (const int*)d_in[22];
    float* outp = (float*)d_out;

    void *p_counts, *p_offsets, *p_cursor, *p_order, *p_uvmap, *p_bufA, *p_bufB;
    void *p_mean, *p_invstd, *p_wtf, *p_wt, *p_ps, *p_pq;
    cudaGetSymbolAddress(&p_counts, g_counts);
    cudaGetSymbolAddress(&p_offsets, g_offsets);
    cudaGetSymbolAddress(&p_cursor, g_cursor);
    cudaGetSymbolAddress(&p_order, g_order);
    cudaGetSymbolAddress(&p_uvmap, g_uvmap);
    cudaGetSymbolAddress(&p_bufA, g_bufA);
    cudaGetSymbolAddress(&p_bufB, g_bufB);
    cudaGetSymbolAddress(&p_mean, g_mean);
    cudaGetSymbolAddress(&p_invstd, g_invstd);
    cudaGetSymbolAddress(&p_wtf, g_wtf);
    cudaGetSymbolAddress(&p_wt, g_wt);
    cudaGetSymbolAddress(&p_ps, g_psum);
    cudaGetSymbolAddress(&p_pq, g_psumsq);

    cudaMemsetAsync(p_counts, 0, 8 * sizeof(int), 0);
    cudaMemsetAsync(p_uvmap, 0, 32 * UVE * sizeof(float), 0);

    wprep_k<<<432, 256>>>(conv_in_w, conv_hid_w, conv_out_w, (float*)p_wtf, (float2*)p_wt);

    int gb = (GN + 255) / 256;
    count_k<<<gb, 256>>>(gs_part, (int*)p_counts);
    scan_k<<<1, 32>>>((const int*)p_counts, (int*)p_offsets, (int*)p_cursor);
    scatter_k<<<gb, 256>>>(gs_part, (int*)p_cursor, (int*)p_order);

    static bool attr_set = false;
    if (!attr_set) {
        cudaFuncSetAttribute(mlp_k, cudaFuncAttributeMaxDynamicSharedMemorySize, 111104);
        attr_set = true;
    }
    mlp_k<<<PN * NT, 256, 111104>>>(
        latent_z, latent_f, cano_xyz,
        m1_w_in, m1_b_in, m1_w_hid, m1_b_hid, m1_w_out, m1_b_out,
        m2_w_in, m2_b_in, m2_w_hid, m2_b_hid, m2_w_out, m2_b_out,
        uv_idx, (const int*)p_order, (const int*)p_offsets, (float*)p_uvmap);

    float* bufA = (float*)p_bufA;
    float* bufB = (float*)p_bufB;
    float* mean = (float*)p_mean;
    float* invstd = (float*)p_invstd;
    float* ps = (float*)p_ps;
    float* pq = (float*)p_pq;
    const float* wtf = (const float*)p_wtf;

    conv64_k<32, false, false, false><<<256, 256>>>((const float*)p_uvmap, wtf, conv_in_b, 0, 0, bufA, 0, 0);
    conv64_k<64, true, false, true><<<256, 256>>>(bufA, wtf + 18432, conv_hid_b, 0, 0, bufB, ps, pq);
    finalize_k<<<64, 256>>>(ps, pq, mean, invstd);
    conv64_k<64, true, true, true><<<256, 256>>>(bufB, wtf + 18432 + 36864, conv_hid_b + 64, mean, invstd, bufA, ps, pq);
    finalize_k<<<64, 256>>>(ps, pq, mean, invstd);
    conv64_k<64, true, true, true><<<256, 256>>>(bufA, wtf + 18432 + 2 * 36864, conv_hid_b + 128, mean, invstd, bufB, ps, pq);
    finalize_k<<<64, 256>>>(ps, pq, mean, invstd);
    convout_k<<<128, 256>>>(bufB, (const float2*)p_wt, conv_out_b, mean, invstd, outp);
}

// round 11
// speedup vs baseline: 1.1819x; 1.0032x over previous
#include <cuda_runtime.h>
#include <math.h>

typedef unsigned long long ull;

#define GN 40000
#define PN 5
#define UVE 65536
#define TM 64
#define NT 625   // ceil(GN/TM)

__device__ __forceinline__ ull fma2(ull a, ull b, ull c) {
    ull d; asm("fma.rn.f32x2 %0, %1, %2, %3;" : "=l"(d) : "l"(a), "l"(b), "l"(c)); return d;
}
__device__ __forceinline__ ull pack2(float lo, float hi) {
    ull d; asm("mov.b64 %0, {%1, %2};" : "=l"(d) : "f"(lo), "f"(hi)); return d;
}
__device__ __forceinline__ void unpack2(ull v, float& lo, float& hi) {
    asm("mov.b64 {%0, %1}, %2;" : "=f"(lo), "=f"(hi) : "l"(v));
}

// ---------- scratch ----------
__device__ int    g_counts[8];
__device__ int    g_offsets[8];
__device__ int    g_cursor[8];
__device__ int    g_order[GN];
__device__ float  g_uvmap[32 * UVE];
__device__ float  g_bufA[64 * UVE];
__device__ float  g_bufB[64 * UVE];
__device__ float  g_mean[64];
__device__ float  g_invstd[64];
__device__ float  g_psum[64 * 512];
__device__ float  g_psumsq[64 * 512];
__device__ float  g_wtf[129024];  // k-major floats: in[cin32][k9][co64]@0 ; hid[l][cin64][k9][co64]@18432
__device__ float2 g_wt[1728];     // convout dup: [cin64][co3][9]

// ---------- bucketing (3-kernel, measured-good) ----------
__global__ void count_k(const int* __restrict__ part, int* counts) {
    int g = blockIdx.x * blockDim.x + threadIdx.x;
    if (g < GN) atomicAdd(&counts[part[g]], 1);
}
__global__ void scan_k(const int* __restrict__ counts, int* offsets, int* cursor) {
    if (threadIdx.x == 0) {
        int s = 0;
        for (int p = 0; p < PN; p++) { offsets[p] = s; cursor[p] = s; s += counts[p]; }
        offsets[PN] = s;
    }
}
__global__ void scatter_k(const int* __restrict__ part, int* cursor, int* __restrict__ order) {
    int g = blockIdx.x * blockDim.x + threadIdx.x;
    if (g < GN) { int pos = atomicAdd(&cursor[part[g]], 1); order[pos] = g; }
}

// ---------- conv weight transpose ----------
__global__ void wprep_k(const float* __restrict__ win, const float* __restrict__ whid,
                        const float* __restrict__ wout, float* __restrict__ wtf,
                        float2* __restrict__ wt) {
    int i = blockIdx.x * 256 + threadIdx.x;
    if (i < 18432) {              // [cin32][k9][co64] <- OIHW [64][32][9]
        int k = i % 9; int t = i / 9; int co = t % 64, cin = t / 64;
        wtf[cin * 576 + k * 64 + co] = win[(co * 32 + cin) * 9 + k];
    }
    if (i < 110592) {             // [l][cin64][k9][co64] <- [l][64][64][9]
        int k = i % 9; int t = i / 9; int co = t % 64;
        int t2 = t / 64; int cin = t2 % 64, l = t2 / 64;
        wtf[18432 + l * 36864 + cin * 576 + k * 64 + co] = whid[((l * 64 + co) * 64 + cin) * 9 + k];
    }
    if (i < 1728) {               // convout dup co-major: [cin64][co3][9] <- [3][64][9]
        int k = i % 9; int t = i / 9; int co = t % 3, cin = t / 3;
        float v = wout[(co * 64 + cin) * 9 + k];
        wt[i] = make_float2(v, v);
    }
}

// ---------- fused MLP: per-warp weight staging (no per-chunk block barrier) ----------
// Warp w owns cols [16w,16w+16); stages its own 16x16 weight slice into a private
// Bs region; only __syncwarp per chunk. One __syncthreads per layer (activation handoff).
__device__ __forceinline__ void layer2(
    const float* A, int K, int NC,
    const float* __restrict__ W, int N, const float* __restrict__ bias,
    float* Out, float* Bs, int tid)
{
    const int w = tid >> 5, lane = tid & 31;
    const int r0 = (lane & 15) << 2;
    const int c0 = (w << 4) + ((lane >> 4) << 3);
    const int wc0 = w << 4;
    const bool active = wc0 < N;

    ull acc[4][4];
#pragma unroll
    for (int r = 0; r < 4; r++)
#pragma unroll
        for (int cp = 0; cp < 4; cp++) acc[r][cp] = 0ull;

    if (active) {
        float* BW = Bs + (w << 9);   // per-warp: 2 buffers x 256 floats

        float wpf[8];
#pragma unroll
        for (int t = 0; t < 8; t++) {
            int e = lane + (t << 5); int kk = e >> 4, j = e & 15;
            wpf[t] = (kk < K && wc0 + j < N) ? W[kk * N + wc0 + j] : 0.f;
        }

        for (int ch = 0; ch < NC; ch++) {
            float* B = BW + ((ch & 1) << 8);
#pragma unroll
            for (int t = 0; t < 8; t++) B[lane + (t << 5)] = wpf[t];
            __syncwarp();
            if (ch + 1 < NC) {
                int kb = (ch + 1) << 4;
#pragma unroll
                for (int t = 0; t < 8; t++) {
                    int e = lane + (t << 5); int kk = kb + (e >> 4), j = e & 15;
                    wpf[t] = (kk < K && wc0 + j < N) ? W[kk * N + wc0 + j] : 0.f;
                }
            }
            const float* Ak = A + (ch << 4) * TM + r0;
            const float* Bk = B + ((lane >> 4) << 3);
#pragma unroll
            for (int kk = 0; kk < 16; kk++) {
                float4 a4 = *(const float4*)(Ak + (kk << 6));
                ulonglong2 b01 = *(const ulonglong2*)(Bk + (kk << 4));
                ulonglong2 b23 = *(const ulonglong2*)(Bk + (kk << 4) + 4);
                ull ar[4] = { pack2(a4.x, a4.x), pack2(a4.y, a4.y),
                              pack2(a4.z, a4.z), pack2(a4.w, a4.w) };
                ull bp[4] = { b01.x, b01.y, b23.x, b23.y };
#pragma unroll
                for (int r = 0; r < 4; r++)
#pragma unroll
                    for (int cp = 0; cp < 4; cp++)
                        acc[r][cp] = fma2(ar[r], bp[cp], acc[r][cp]);
            }
        }

#pragma unroll
        for (int cp = 0; cp < 4; cp++) {
            int c = c0 + (cp << 1);
            float lo, hi;
            float blo = bias[c], bhi = bias[c + 1];
#pragma unroll
            for (int r = 0; r < 4; r++) {
                unpack2(acc[r][cp], lo, hi);
                lo += blo; hi += bhi;
                Out[c * TM + r0 + r]       = lo > 0.f ? lo : 0.01f * lo;
                Out[(c + 1) * TM + r0 + r] = hi > 0.f ? hi : 0.01f * hi;
            }
        }
    }
    __syncthreads();   // activation handoff (Out -> next layer's A) + Bs reuse guard
}

// Row-spread output layer (small N): cooperative staging (unchanged, 2 uses only).
template<int NJ, bool SCATTER>
__device__ __forceinline__ void layer_rs(
    const float* A, int K, int NC,
    const float* __restrict__ W, int N, const float* __restrict__ bias,
    float* Out, float* Bs, int tid,
    const int* s_uv, float* uvmap, int m)
{
    const int w = tid >> 5, lane = tid & 31;
    const int r = (w << 3) + (lane >> 2);
    const int cg4 = lane & 3;

    float acc[NJ];
#pragma unroll
    for (int j = 0; j < NJ; j++) acc[j] = 0.f;

    float wpf[8];
#pragma unroll
    for (int t = 0; t < 8; t++) {
        int e = tid + (t << 8); int kk = e >> 7, j = e & 127;
        wpf[t] = (kk < K && j < N) ? W[kk * N + j] : 0.f;
    }

    for (int ch = 0; ch < NC; ch++) {
        float* B = Bs + ((ch & 1) << 11);
#pragma unroll
        for (int t = 0; t < 8; t++) B[tid + (t << 8)] = wpf[t];
        __syncthreads();
        if (ch + 1 < NC) {
            int kb = (ch + 1) << 4;
#pragma unroll
            for (int t = 0; t < 8; t++) {
                int e = tid + (t << 8); int kk = kb + (e >> 7), j = e & 127;
                wpf[t] = (kk < K && j < N) ? W[kk * N + j] : 0.f;
            }
        }
        const float* Ak = A + (ch << 4) * TM + r;
#pragma unroll
        for (int kk = 0; kk < 16; kk++) {
            float a = Ak[kk << 6];
            const float* Bk = B + (kk << 7) + cg4;
#pragma unroll
            for (int j = 0; j < NJ; j++)
                acc[j] += a * Bk[j << 2];
        }
        __syncthreads();
    }

    if (!SCATTER) {
#pragma unroll
        for (int j = 0; j < NJ; j++) {
            int c = cg4 + (j << 2);
            if (c < N) Out[c * TM + r] = acc[j] + bias[c];
        }
    } else {
        if (r < m) {
            int uv = s_uv[r];
#pragma unroll
            for (int j = 0; j < NJ; j++) {
                int c = cg4 + (j << 2);
                if (c < N) uvmap[c * UVE + uv] = acc[j] + bias[c];
            }
        }
    }
    __syncthreads();
}

__global__ __launch_bounds__(256, 2)
void mlp_k(const float* __restrict__ latent_z, const float* __restrict__ latent_f,
           const float* __restrict__ cano_xyz,
           const float* __restrict__ m1_w_in, const float* __restrict__ m1_b_in,
           const float* __restrict__ m1_w_hid, const float* __restrict__ m1_b_hid,
           const float* __restrict__ m1_w_out, const float* __restrict__ m1_b_out,
           const float* __restrict__ m2_w_in, const float* __restrict__ m2_b_in,
           const float* __restrict__ m2_w_hid, const float* __restrict__ m2_b_hid,
           const float* __restrict__ m2_w_out, const float* __restrict__ m2_b_out,
           const int* __restrict__ uv_idx,
           const int* __restrict__ order, const int* __restrict__ offsets,
           float* __restrict__ uvmap)
{
    extern __shared__ float sm[];
    float* Xs = sm;                        // [112][64]
    float* Hp = Xs + 112 * TM;             // [128][64]
    float* Hq = Hp + 128 * TM;             // [128][64]
    float* Bs = Hq + 128 * TM;             // 4096 floats (per-warp or cooperative layout)
    int*   s_idx = (int*)(Bs + 4096);      // [64]
    int*   s_uv  = s_idx + TM;             // [64]

    int p = blockIdx.x / NT;
    int t = blockIdx.x % NT;
    int beg = offsets[p], end = offsets[p + 1];
    int start = beg + t * TM;
    if (start >= end) return;
    int m = min(TM, end - start);
    int tid = threadIdx.x;

    if (tid < TM) {
        int rr = tid < m ? tid : (m - 1);
        int gid = order[start + rr];
        s_idx[tid] = gid;
        s_uv[tid] = uv_idx[gid];
    }
    __syncthreads();

    for (int e = tid; e < 112 * TM; e += 256) {
        int d = e >> 6, r = e & 63;
        float v = 0.f;
        if (d < 64)       v = latent_f[p * 64 + d];
        else if (d < 96)  v = latent_z[s_idx[r] * 32 + (d - 64)];
        else if (d < 99)  v = cano_xyz[s_idx[r] * 3 + (d - 96)];
        Xs[e] = v;
    }
    __syncthreads();

    layer2(Xs, 96, 6,  m1_w_in  + p * 96 * 128, 128, m1_b_in  + p * 128, Hp, Bs, tid);
    layer2(Hp, 128, 8, m1_w_hid + (p * 2 + 0) * 16384, 128, m1_b_hid + (p * 2 + 0) * 128, Hq, Bs, tid);
    layer2(Hq, 128, 8, m1_w_hid + (p * 2 + 1) * 16384, 128, m1_b_hid + (p * 2 + 1) * 128, Hp, Bs, tid);
    layer_rs<3, false>(Hp, 128, 8, m1_w_out + p * 128 * 11, 11, m1_b_out + p * 11, Xs + 99 * TM, Bs, tid, 0, 0, m);
    layer2(Xs, 110, 7, m2_w_in  + p * 110 * 128, 128, m2_b_in  + p * 128, Hp, Bs, tid);
    layer2(Hp, 128, 8, m2_w_hid + (p * 2 + 0) * 16384, 128, m2_b_hid + (p * 2 + 0) * 128, Hq, Bs, tid);
    layer2(Hq, 128, 8, m2_w_hid + (p * 2 + 1) * 16384, 128, m2_b_hid + (p * 2 + 1) * 128, Hp, Bs, tid);
    layer_rs<8, true>(Hp, 128, 8, m2_w_out + p * 128 * 32, 32, m2_b_out + p * 32, (float*)0, Bs, tid, s_uv, uvmap, m);
}

// ---------- CNN ----------
template<bool NORM, bool RELU, int TW>
__device__ __forceinline__ float conv_val(const float* __restrict__ in, int cin,
                                          int x0, int y0, int e, float mn, float is) {
    int row = e / TW, col = e - row * TW;
    int iy = y0 + row - 1, ix = x0 + col - 1;
    float v = 0.f;
    if (iy >= 0 && iy < 256 && ix >= 0 && ix < 256) {
        v = in[cin * UVE + iy * 256 + ix];
        if (NORM) v = (v - mn) * is;
        if (RELU) v = fmaxf(v, 0.f);
    }
    return v;
}

// 16x16 px x 64 co per block. Thread: 2x2 px (pg) x 16 co (cg). f32x2 packed over COUT pairs.
template<int CIN, bool RELU, bool NORM, bool STATS>
__global__ __launch_bounds__(256, 2)
void conv64_k(const float* __restrict__ in, const float* __restrict__ wtf,
              const float* __restrict__ bias,
              const float* __restrict__ mean, const float* __restrict__ invstd,
              float* __restrict__ out,
              float* __restrict__ psum, float* __restrict__ psumsq)
{
    __shared__ __align__(16) ull   tD[2][324];
    __shared__ __align__(16) float wsf[2][576];

    const int bx = blockIdx.x;
    const int x0 = (bx & 15) << 4, y0 = (bx >> 4) << 4;
    const int tid = threadIdx.x;
    const int pg = tid & 63, cg = tid >> 6;
    const int lx = (pg & 7) << 1, ly = (pg >> 3) << 1;

    ull acc[8][4];   // [copair][q = dy*2+dx]
#pragma unroll
    for (int cp = 0; cp < 8; cp++)
#pragma unroll
        for (int q = 0; q < 4; q++) acc[cp][q] = 0ull;

    float tv0, tv1 = 0.f;
    float wv0, wv1, wv2 = 0.f;
    {
        float mn = NORM ? mean[0] : 0.f, is = NORM ? invstd[0] : 1.f;
        tv0 = conv_val<NORM, RELU, 18>(in, 0, x0, y0, tid, mn, is);
        if (tid < 68) tv1 = conv_val<NORM, RELU, 18>(in, 0, x0, y0, tid + 256, mn, is);
        wv0 = wtf[tid]; wv1 = wtf[tid + 256];
        if (tid < 64) wv2 = wtf[tid + 512];
    }

    for (int cin = 0; cin < CIN; cin++) {
        const int b = cin & 1;
        tD[b][tid] = pack2(tv0, tv0);
        if (tid < 68) tD[b][tid + 256] = pack2(tv1, tv1);
        wsf[b][tid] = wv0; wsf[b][tid + 256] = wv1;
        if (tid < 64) wsf[b][tid + 512] = wv2;
        __syncthreads();
        if (cin + 1 < CIN) {
            int c2 = cin + 1;
            float mn = NORM ? mean[c2] : 0.f, is = NORM ? invstd[c2] : 1.f;
            tv0 = conv_val<NORM, RELU, 18>(in, c2, x0, y0, tid, mn, is);
            if (tid < 68) tv1 = conv_val<NORM, RELU, 18>(in, c2, x0, y0, tid + 256, mn, is);
            const float* wp = wtf + c2 * 576;
            wv0 = wp[tid]; wv1 = wp[tid + 256];
            if (tid < 64) wv2 = wp[tid + 512];
        }
        const ull* td = tD[b];
        const float* wk = wsf[b] + (cg << 4);
#pragma unroll
        for (int ky = 0; ky < 3; ky++) {
            ulonglong2 ra0 = *(const ulonglong2*)&td[(ly + ky) * 18 + lx];
            ulonglong2 ra1 = *(const ulonglong2*)&td[(ly + ky) * 18 + lx + 2];
            ulonglong2 rb0 = *(const ulonglong2*)&td[(ly + ky + 1) * 18 + lx];
            ulonglong2 rb1 = *(const ulonglong2*)&td[(ly + ky + 1) * 18 + lx + 2];
            ull pa[4] = { ra0.x, ra0.y, ra1.x, ra1.y };
            ull pb[4] = { rb0.x, rb0.y, rb1.x, rb1.y };
#pragma unroll
            for (int kx = 0; kx < 3; kx++) {
#pragma unroll
                for (int cp2 = 0; cp2 < 4; cp2++) {
                    ulonglong2 w2 = *(const ulonglong2*)&wk[(ky * 3 + kx) * 64 + (cp2 << 2)];
                    int ce = cp2 << 1;
                    acc[ce][0]     = fma2(pa[kx],     w2.x, acc[ce][0]);
                    acc[ce][1]     = fma2(pa[kx + 1], w2.x, acc[ce][1]);
                    acc[ce][2]     = fma2(pb[kx],     w2.x, acc[ce][2]);
                    acc[ce][3]     = fma2(pb[kx + 1], w2.x, acc[ce][3]);
                    acc[ce + 1][0] = fma2(pa[kx],     w2.y, acc[ce + 1][0]);
                    acc[ce + 1][1] = fma2(pa[kx + 1], w2.y, acc[ce + 1][1]);
                    acc[ce + 1][2] = fma2(pb[kx],     w2.y, acc[ce + 1][2]);
                    acc[ce + 1][3] = fma2(pb[kx + 1], w2.y, acc[ce + 1][3]);
                }
            }
        }
    }

    const int wpar = (tid >> 5) & 1;
#pragma unroll
    for (int cp = 0; cp < 8; cp++) {
        int cA = (cg << 4) + (cp << 1), cB = cA + 1;
        float bA = bias[cA], bB = bias[cB];
        float vA[4], vB[4];
#pragma unroll
        for (int q = 0; q < 4; q++) {
            unpack2(acc[cp][q], vA[q], vB[q]);
            vA[q] += bA; vB[q] += bB;
        }
        float* opA = out + cA * UVE + (y0 + ly) * 256 + (x0 + lx);
        float* opB = out + cB * UVE + (y0 + ly) * 256 + (x0 + lx);
        *(float2*)opA         = make_float2(vA[0], vA[1]);
        *(float2*)(opA + 256) = make_float2(vA[2], vA[3]);
        *(float2*)opB         = make_float2(vB[0], vB[1]);
        *(float2*)(opB + 256) = make_float2(vB[2], vB[3]);
        if (STATS) {
            float sA = vA[0] + vA[1] + vA[2] + vA[3];
            float qA = vA[0] * vA[0] + vA[1] * vA[1] + vA[2] * vA[2] + vA[3] * vA[3];
            float sB = vB[0] + vB[1] + vB[2] + vB[3];
            float qB = vB[0] * vB[0] + vB[1] * vB[1] + vB[2] * vB[2] + vB[3] * vB[3];
#pragma unroll
            for (int d = 16; d >= 1; d >>= 1) {
                sA += __shfl_down_sync(0xffffffffu, sA, d);
                qA += __shfl_down_sync(0xffffffffu, qA, d);
                sB += __shfl_down_sync(0xffffffffu, sB, d);
                qB += __shfl_down_sync(0xffffffffu, qB, d);
            }
            if ((tid & 31) == 0) {
                psum[cA * 512 + (bx << 1) + wpar] = sA;
                psumsq[cA * 512 + (bx << 1) + wpar] = qA;
                psum[cB * 512 + (bx << 1) + wpar] = sB;
                psumsq[cB * 512 + (bx << 1) + wpar] = qB;
            }
        }
    }
}

__global__ void finalize_k(const float* __restrict__ psum, const float* __restrict__ psumsq,
                           float* __restrict__ mean, float* __restrict__ invstd) {
    __shared__ float s1[256], s2[256];
    int c = blockIdx.x, tid = threadIdx.x;
    s1[tid] = psum[c * 512 + tid] + psum[c * 512 + 256 + tid];
    s2[tid] = psumsq[c * 512 + tid] + psumsq[c * 512 + 256 + tid];
    __syncthreads();
    for (int s = 128; s > 0; s >>= 1) {
        if (tid < s) { s1[tid] += s1[tid + s]; s2[tid] += s2[tid + s]; }
        __syncthreads();
    }
    if (tid == 0) {
        float mu = s1[0] * (1.f / UVE);
        float var = s2[0] * (1.f / UVE) - mu * mu;
        mean[c] = mu;
        invstd[c] = rsqrtf(var + 1e-5f);
    }
}

// conv_out: 64 -> 3, normalized input, sigmoid. Block 32x16 px; thread = 1 px pair x 3 couts.
__global__ __launch_bounds__(256, 2)
void convout_k(const float* __restrict__ in, const float2* __restrict__ wt,
               const float* __restrict__ bias,
               const float* __restrict__ mean, const float* __restrict__ invstd,
               float* __restrict__ out)
{
    __shared__ __align__(16) float tA[2][612];
    __shared__ __align__(16) float tB[2][616];
    __shared__ __align__(16) float2 wds[1728];

    const int bx = blockIdx.x;
    const int x0 = (bx & 7) << 5, y0 = (bx >> 3) << 4;
    const int tid = threadIdx.x;
    const int lx = (tid & 15) << 1, ly = tid >> 4;

    for (int e = tid; e < 1728; e += 256) wds[e] = wt[e];

    ull acc0 = 0ull, acc1 = 0ull, acc2 = 0ull;

    float tv0, tv1 = 0.f, tv2 = 0.f;
    {
        float mn = mean[0], is = invstd[0];
        tv0 = conv_val<true, false, 34>(in, 0, x0, y0, tid, mn, is);
        tv1 = conv_val<true, false, 34>(in, 0, x0, y0, tid + 256, mn, is);
        if (tid < 100) tv2 = conv_val<true, false, 34>(in, 0, x0, y0, tid + 512, mn, is);
    }

    for (int cin = 0; cin < 64; cin++) {
        const int b = cin & 1;
        tA[b][tid] = tv0; tB[b][tid + 1] = tv0;
        tA[b][tid + 256] = tv1; tB[b][tid + 257] = tv1;
        if (tid < 100) { tA[b][tid + 512] = tv2; tB[b][tid + 513] = tv2; }
        __syncthreads();
        if (cin + 1 < 64) {
            int c2 = cin + 1;
            float mn = mean[c2], is = invstd[c2];
            tv0 = conv_val<true, false, 34>(in, c2, x0, y0, tid, mn, is);
            tv1 = conv_val<true, false, 34>(in, c2, x0, y0, tid + 256, mn, is);
            if (tid < 100) tv2 = conv_val<true, false, 34>(in, c2, x0, y0, tid + 512, mn, is);
        }
        ull pp[3][3];
#pragma unroll
        for (int r = 0; r < 3; r++) {
            int base = (ly + r) * 34 + lx;
            pp[r][0] = *(const ull*)&tA[b][base];
            pp[r][1] = *(const ull*)&tB[b][base + 2];
            pp[r][2] = *(const ull*)&tA[b][base + 2];
        }
        const float2* wc = wds + cin * 27;
#pragma unroll
        for (int r = 0; r < 3; r++)
#pragma unroll
            for (int kx = 0; kx < 3; kx++) {
                acc0 = fma2(pp[r][kx], *(const ull*)&wc[r * 3 + kx],      acc0);
                acc1 = fma2(pp[r][kx], *(const ull*)&wc[9 + r * 3 + kx],  acc1);
                acc2 = fma2(pp[r][kx], *(const ull*)&wc[18 + r * 3 + kx], acc2);
            }
        __syncthreads();
    }

    int o = (y0 + ly) * 256 + x0 + lx;
    float lo, hi;
    unpack2(acc0, lo, hi);
    *(float2*)(out + o) = make_float2(1.f / (1.f + __expf(-(lo + bias[0]))),
                                      1.f / (1.f + __expf(-(hi + bias[0]))));
    unpack2(acc1, lo, hi);
    *(float2*)(out + UVE + o) = make_float2(1.f / (1.f + __expf(-(lo + bias[1]))),
                                            1.f / (1.f + __expf(-(hi + bias[1]))));
    unpack2(acc2, lo, hi);
    *(float2*)(out + 2 * UVE + o) = make_float2(1.f / (1.f + __expf(-(lo + bias[2]))),
                                                1.f / (1.f + __expf(-(hi + bias[2]))));
}

// ---------- launch ----------
extern "C" void kernel_launch(void* const* d_in, const int* in_sizes, int n_in,
                              void* d_out, int out_size)
{
    const float* latent_z  = (const float*)d_in[0];
    const float* latent_f  = (const float*)d_in[1];
    const float* cano_xyz  = (const float*)d_in[2];
    const float* m1_w_in   = (const float*)d_in[3];
    const float* m1_b_in   = (const float*)d_in[4];
    const float* m1_w_hid  = (const float*)d_in[5];
    const float* m1_b_hid  = (const float*)d_in[6];
    const float* m1_w_out  = (const float*)d_in[7];
    const float* m1_b_out  = (const float*)d_in[8];
    const float* m2_w_in   = (const float*)d_in[9];
    const float* m2_b_in   = (const float*)d_in[10];
    const float* m2_w_hid  = (const float*)d_in[11];
    const float* m2_b_hid  = (const float*)d_in[12];
    const float* m2_w_out  = (const float*)d_in[13];
    const float* m2_b_out  = (const float*)d_in[14];
    const float* conv_in_w = (const float*)d_in[15];
    const float* conv_in_b = (const float*)d_in[16];
    const float* conv_hid_w= (const float*)d_in[17];
    const float* conv_hid_b= (const float*)d_in[18];
    const float* conv_out_w= (const float*)d_in[19];
    const float* conv_out_b= (const float*)d_in[20];
    const int*   gs_part   = (const int*)d_in[21];
    const int*   uv_idx    = (const int*)d_in[22];
    float* outp = (float*)d_out;

    void *p_counts, *p_offsets, *p_cursor, *p_order, *p_uvmap, *p_bufA, *p_bufB;
    void *p_mean, *p_invstd, *p_wtf, *p_wt, *p_ps, *p_pq;
    cudaGetSymbolAddress(&p_counts, g_counts);
    cudaGetSymbolAddress(&p_offsets, g_offsets);
    cudaGetSymbolAddress(&p_cursor, g_cursor);
    cudaGetSymbolAddress(&p_order, g_order);
    cudaGetSymbolAddress(&p_uvmap, g_uvmap);
    cudaGetSymbolAddress(&p_bufA, g_bufA);
    cudaGetSymbolAddress(&p_bufB, g_bufB);
    cudaGetSymbolAddress(&p_mean, g_mean);
    cudaGetSymbolAddress(&p_invstd, g_invstd);
    cudaGetSymbolAddress(&p_wtf, g_wtf);
    cudaGetSymbolAddress(&p_wt, g_wt);
    cudaGetSymbolAddress(&p_ps, g_psum);
    cudaGetSymbolAddress(&p_pq, g_psumsq);

    cudaMemsetAsync(p_counts, 0, 8 * sizeof(int), 0);
    cudaMemsetAsync(p_uvmap, 0, 32 * UVE * sizeof(float), 0);

    wprep_k<<<432, 256>>>(conv_in_w, conv_hid_w, conv_out_w, (float*)p_wtf, (float2*)p_wt);

    int gb = (GN + 255) / 256;
    count_k<<<gb, 256>>>(gs_part, (int*)p_counts);
    scan_k<<<1, 32>>>((const int*)p_counts, (int*)p_offsets, (int*)p_cursor);
    scatter_k<<<gb, 256>>>(gs_part, (int*)p_cursor, (int*)p_order);

    static bool attr_set = false;
    if (!attr_set) {
        cudaFuncSetAttribute(mlp_k, cudaFuncAttributeMaxDynamicSharedMemorySize, 111104);
        attr_set = true;
    }
    mlp_k<<<PN * NT, 256, 111104>>>(
        latent_z, latent_f, cano_xyz,
        m1_w_in, m1_b_in, m1_w_hid, m1_b_hid, m1_w_out, m1_b_out,
        m2_w_in, m2_b_in, m2_w_hid, m2_b_hid, m2_w_out, m2_b_out,
        uv_idx, (const int*)p_order, (const int*)p_offsets, (float*)p_uvmap);

    float* bufA = (float*)p_bufA;
    float* bufB = (float*)p_bufB;
    float* mean = (float*)p_mean;
    float* invstd = (float*)p_invstd;
    float* ps = (float*)p_ps;
    float* pq = (float*)p_pq;
    const float* wtf = (const float*)p_wtf;

    conv64_k<32, false, false, false><<<256, 256>>>((const float*)p_uvmap, wtf, conv_in_b, 0, 0, bufA, 0, 0);
    conv64_k<64, true, false, true><<<256, 256>>>(bufA, wtf + 18432, conv_hid_b, 0, 0, bufB, ps, pq);
    finalize_k<<<64, 256>>>(ps, pq, mean, invstd);
    conv64_k<64, true, true, true><<<256, 256>>>(bufB, wtf + 18432 + 36864, conv_hid_b + 64, mean, invstd, bufA, ps, pq);
    finalize_k<<<64, 256>>>(ps, pq, mean, invstd);
    conv64_k<64, true, true, true><<<256, 256>>>(bufA, wtf + 18432 + 2 * 36864, conv_hid_b + 128, mean, invstd, bufB, ps, pq);
    finalize_k<<<64, 256>>>(ps, pq, mean, invstd);
    convout_k<<<128, 256>>>(bufB, (const float2*)p_wt, conv_out_b, mean, invstd, outp);
}

// round 12
// speedup vs baseline: 1.1838x; 1.0016x over previous
#include <cuda_runtime.h>
#include <math.h>

typedef unsigned long long ull;

#define GN 40000
#define PN 5
#define UVE 65536
#define TM 64
#define NT 625   // ceil(GN/TM)

__device__ __forceinline__ ull fma2(ull a, ull b, ull c) {
    ull d; asm("fma.rn.f32x2 %0, %1, %2, %3;" : "=l"(d) : "l"(a), "l"(b), "l"(c)); return d;
}
__device__ __forceinline__ ull pack2(float lo, float hi) {
    ull d; asm("mov.b64 %0, {%1, %2};" : "=l"(d) : "f"(lo), "f"(hi)); return d;
}
__device__ __forceinline__ void unpack2(ull v, float& lo, float& hi) {
    asm("mov.b64 {%0, %1}, %2;" : "=f"(lo), "=f"(hi) : "l"(v));
}

// ---------- scratch ----------
__device__ int    g_counts[8];
__device__ int    g_offsets[8];
__device__ int    g_cursor[8];
__device__ int    g_order[GN];
__device__ float  g_uvmap[32 * UVE];
__device__ float  g_bufA[64 * UVE];
__device__ float  g_bufB[64 * UVE];
__device__ float  g_psumA[64 * 512];
__device__ float  g_psumsqA[64 * 512];
__device__ float  g_psumB[64 * 512];
__device__ float  g_psumsqB[64 * 512];
__device__ float  g_wtf[129024];  // k-major floats: in[cin32][k9][co64]@0 ; hid[l][cin64][k9][co64]@18432
__device__ float2 g_wt[1728];     // convout dup: [cin64][co3][9]

// ---------- bucketing (3-kernel, measured-good) ----------
__global__ void count_k(const int* __restrict__ part, int* counts) {
    int g = blockIdx.x * blockDim.x + threadIdx.x;
    if (g < GN) atomicAdd(&counts[part[g]], 1);
}
__global__ void scan_k(const int* __restrict__ counts, int* offsets, int* cursor) {
    if (threadIdx.x == 0) {
        int s = 0;
        for (int p = 0; p < PN; p++) { offsets[p] = s; cursor[p] = s; s += counts[p]; }
        offsets[PN] = s;
    }
}
__global__ void scatter_k(const int* __restrict__ part, int* cursor, int* __restrict__ order) {
    int g = blockIdx.x * blockDim.x + threadIdx.x;
    if (g < GN) { int pos = atomicAdd(&cursor[part[g]], 1); order[pos] = g; }
}

// ---------- conv weight transpose ----------
__global__ void wprep_k(const float* __restrict__ win, const float* __restrict__ whid,
                        const float* __restrict__ wout, float* __restrict__ wtf,
                        float2* __restrict__ wt) {
    int i = blockIdx.x * 256 + threadIdx.x;
    if (i < 18432) {              // [cin32][k9][co64] <- OIHW [64][32][9]
        int k = i % 9; int t = i / 9; int co = t % 64, cin = t / 64;
        wtf[cin * 576 + k * 64 + co] = win[(co * 32 + cin) * 9 + k];
    }
    if (i < 110592) {             // [l][cin64][k9][co64] <- [l][64][64][9]
        int k = i % 9; int t = i / 9; int co = t % 64;
        int t2 = t / 64; int cin = t2 % 64, l = t2 / 64;
        wtf[18432 + l * 36864 + cin * 576 + k * 64 + co] = whid[((l * 64 + co) * 64 + cin) * 9 + k];
    }
    if (i < 1728) {               // convout dup co-major: [cin64][co3][9] <- [3][64][9]
        int k = i % 9; int t = i / 9; int co = t % 3, cin = t / 3;
        float v = wout[(co * 64 + cin) * 9 + k];
        wt[i] = make_float2(v, v);
    }
}

// ---------- fused MLP: per-warp weight staging ----------
__device__ __forceinline__ void layer2(
    const float* A, int K, int NC,
    const float* __restrict__ W, int N, const float* __restrict__ bias,
    float* Out, float* Bs, int tid)
{
    const int w = tid >> 5, lane = tid & 31;
    const int r0 = (lane & 15) << 2;
    const int c0 = (w << 4) + ((lane >> 4) << 3);
    const int wc0 = w << 4;
    const bool active = wc0 < N;

    ull acc[4][4];
#pragma unroll
    for (int r = 0; r < 4; r++)
#pragma unroll
        for (int cp = 0; cp < 4; cp++) acc[r][cp] = 0ull;

    if (active) {
        float* BW = Bs + (w << 9);

        float wpf[8];
#pragma unroll
        for (int t = 0; t < 8; t++) {
            int e = lane + (t << 5); int kk = e >> 4, j = e & 15;
            wpf[t] = (kk < K && wc0 + j < N) ? W[kk * N + wc0 + j] : 0.f;
        }

        for (int ch = 0; ch < NC; ch++) {
            float* B = BW + ((ch & 1) << 8);
#pragma unroll
            for (int t = 0; t < 8; t++) B[lane + (t << 5)] = wpf[t];
            __syncwarp();
            if (ch + 1 < NC) {
                int kb = (ch + 1) << 4;
#pragma unroll
                for (int t = 0; t < 8; t++) {
                    int e = lane + (t << 5); int kk = kb + (e >> 4), j = e & 15;
                    wpf[t] = (kk < K && wc0 + j < N) ? W[kk * N + wc0 + j] : 0.f;
                }
            }
            const float* Ak = A + (ch << 4) * TM + r0;
            const float* Bk = B + ((lane >> 4) << 3);
#pragma unroll
            for (int kk = 0; kk < 16; kk++) {
                float4 a4 = *(const float4*)(Ak + (kk << 6));
                ulonglong2 b01 = *(const ulonglong2*)(Bk + (kk << 4));
                ulonglong2 b23 = *(const ulonglong2*)(Bk + (kk << 4) + 4);
                ull ar[4] = { pack2(a4.x, a4.x), pack2(a4.y, a4.y),
                              pack2(a4.z, a4.z), pack2(a4.w, a4.w) };
                ull bp[4] = { b01.x, b01.y, b23.x, b23.y };
#pragma unroll
                for (int r = 0; r < 4; r++)
#pragma unroll
                    for (int cp = 0; cp < 4; cp++)
                        acc[r][cp] = fma2(ar[r], bp[cp], acc[r][cp]);
            }
        }

#pragma unroll
        for (int cp = 0; cp < 4; cp++) {
            int c = c0 + (cp << 1);
            float lo, hi;
            float blo = bias[c], bhi = bias[c + 1];
#pragma unroll
            for (int r = 0; r < 4; r++) {
                unpack2(acc[r][cp], lo, hi);
                lo += blo; hi += bhi;
                Out[c * TM + r0 + r]       = lo > 0.f ? lo : 0.01f * lo;
                Out[(c + 1) * TM + r0 + r] = hi > 0.f ? hi : 0.01f * hi;
            }
        }
    }
    __syncthreads();
}

// Row-spread output layer (small N)
template<int NJ, bool SCATTER>
__device__ __forceinline__ void layer_rs(
    const float* A, int K, int NC,
    const float* __restrict__ W, int N, const float* __restrict__ bias,
    float* Out, float* Bs, int tid,
    const int* s_uv, float* uvmap, int m)
{
    const int w = tid >> 5, lane = tid & 31;
    const int r = (w << 3) + (lane >> 2);
    const int cg4 = lane & 3;

    float acc[NJ];
#pragma unroll
    for (int j = 0; j < NJ; j++) acc[j] = 0.f;

    float wpf[8];
#pragma unroll
    for (int t = 0; t < 8; t++) {
        int e = tid + (t << 8); int kk = e >> 7, j = e & 127;
        wpf[t] = (kk < K && j < N) ? W[kk * N + j] : 0.f;
    }

    for (int ch = 0; ch < NC; ch++) {
        float* B = Bs + ((ch & 1) << 11);
#pragma unroll
        for (int t = 0; t < 8; t++) B[tid + (t << 8)] = wpf[t];
        __syncthreads();
        if (ch + 1 < NC) {
            int kb = (ch + 1) << 4;
#pragma unroll
            for (int t = 0; t < 8; t++) {
                int e = tid + (t << 8); int kk = kb + (e >> 7), j = e & 127;
                wpf[t] = (kk < K && j < N) ? W[kk * N + j] : 0.f;
            }
        }
        const float* Ak = A + (ch << 4) * TM + r;
#pragma unroll
        for (int kk = 0; kk < 16; kk++) {
            float a = Ak[kk << 6];
            const float* Bk = B + (kk << 7) + cg4;
#pragma unroll
            for (int j = 0; j < NJ; j++)
                acc[j] += a * Bk[j << 2];
        }
        __syncthreads();
    }

    if (!SCATTER) {
#pragma unroll
        for (int j = 0; j < NJ; j++) {
            int c = cg4 + (j << 2);
            if (c < N) Out[c * TM + r] = acc[j] + bias[c];
        }
    } else {
        if (r < m) {
            int uv = s_uv[r];
#pragma unroll
            for (int j = 0; j < NJ; j++) {
                int c = cg4 + (j << 2);
                if (c < N) uvmap[c * UVE + uv] = acc[j] + bias[c];
            }
        }
    }
    __syncthreads();
}

__global__ __launch_bounds__(256, 2)
void mlp_k(const float* __restrict__ latent_z, const float* __restrict__ latent_f,
           const float* __restrict__ cano_xyz,
           const float* __restrict__ m1_w_in, const float* __restrict__ m1_b_in,
           const float* __restrict__ m1_w_hid, const float* __restrict__ m1_b_hid,
           const float* __restrict__ m1_w_out, const float* __restrict__ m1_b_out,
           const float* __restrict__ m2_w_in, const float* __restrict__ m2_b_in,
           const float* __restrict__ m2_w_hid, const float* __restrict__ m2_b_hid,
           const float* __restrict__ m2_w_out, const float* __restrict__ m2_b_out,
           const int* __restrict__ uv_idx,
           const int* __restrict__ order, const int* __restrict__ offsets,
           float* __restrict__ uvmap)
{
    extern __shared__ float sm[];
    float* Xs = sm;                        // [112][64]
    float* Hp = Xs + 112 * TM;             // [128][64]
    float* Hq = Hp + 128 * TM;             // [128][64]
    float* Bs = Hq + 128 * TM;             // 4096 floats
    int*   s_idx = (int*)(Bs + 4096);      // [64]
    int*   s_uv  = s_idx + TM;             // [64]

    int p = blockIdx.x / NT;
    int t = blockIdx.x % NT;
    int beg = offsets[p], end = offsets[p + 1];
    int start = beg + t * TM;
    if (start >= end) return;
    int m = min(TM, end - start);
    int tid = threadIdx.x;

    if (tid < TM) {
        int rr = tid < m ? tid : (m - 1);
        int gid = order[start + rr];
        s_idx[tid] = gid;
        s_uv[tid] = uv_idx[gid];
    }
    __syncthreads();

    for (int e = tid; e < 112 * TM; e += 256) {
        int d = e >> 6, r = e & 63;
        float v = 0.f;
        if (d < 64)       v = latent_f[p * 64 + d];
        else if (d < 96)  v = latent_z[s_idx[r] * 32 + (d - 64)];
        else if (d < 99)  v = cano_xyz[s_idx[r] * 3 + (d - 96)];
        Xs[e] = v;
    }
    __syncthreads();

    layer2(Xs, 96, 6,  m1_w_in  + p * 96 * 128, 128, m1_b_in  + p * 128, Hp, Bs, tid);
    layer2(Hp, 128, 8, m1_w_hid + (p * 2 + 0) * 16384, 128, m1_b_hid + (p * 2 + 0) * 128, Hq, Bs, tid);
    layer2(Hq, 128, 8, m1_w_hid + (p * 2 + 1) * 16384, 128, m1_b_hid + (p * 2 + 1) * 128, Hp, Bs, tid);
    layer_rs<3, false>(Hp, 128, 8, m1_w_out + p * 128 * 11, 11, m1_b_out + p * 11, Xs + 99 * TM, Bs, tid, 0, 0, m);
    layer2(Xs, 110, 7, m2_w_in  + p * 110 * 128, 128, m2_b_in  + p * 128, Hp, Bs, tid);
    layer2(Hp, 128, 8, m2_w_hid + (p * 2 + 0) * 16384, 128, m2_b_hid + (p * 2 + 0) * 128, Hq, Bs, tid);
    layer2(Hq, 128, 8, m2_w_hid + (p * 2 + 1) * 16384, 128, m2_b_hid + (p * 2 + 1) * 128, Hp, Bs, tid);
    layer_rs<8, true>(Hp, 128, 8, m2_w_out + p * 128 * 32, 32, m2_b_out + p * 32, (float*)0, Bs, tid, s_uv, uvmap, m);
}

// ---------- CNN ----------
template<bool NORM, bool RELU, int TW>
__device__ __forceinline__ float conv_val(const float* __restrict__ in, int cin,
                                          int x0, int y0, int e, float mn, float is) {
    int row = e / TW, col = e - row * TW;
    int iy = y0 + row - 1, ix = x0 + col - 1;
    float v = 0.f;
    if (iy >= 0 && iy < 256 && ix >= 0 && ix < 256) {
        v = in[cin * UVE + iy * 256 + ix];
        if (NORM) v = (v - mn) * is;
        if (RELU) v = fmaxf(v, 0.f);
    }
    return v;
}

// 16x16 px x 64 co per block. Thread: 2x2 px (pg) x 16 co (cg). f32x2 packed over COUT pairs.
// NORM: per-block prologue reduces psum partials -> smem mean/invstd (no finalize kernel).
template<int CIN, bool RELU, bool NORM, bool STATS>
__global__ __launch_bounds__(256, 2)
void conv64_k(const float* __restrict__ in, const float* __restrict__ wtf,
              const float* __restrict__ bias,
              const float* __restrict__ ps_in, const float* __restrict__ pq_in,
              float* __restrict__ out,
              float* __restrict__ ps_out, float* __restrict__ pq_out)
{
    __shared__ __align__(16) ull   tD[2][324];
    __shared__ __align__(16) float wsf[2][576];
    __shared__ float s_mn[64], s_is[64];

    const int bx = blockIdx.x;
    const int x0 = (bx & 15) << 4, y0 = (bx >> 4) << 4;
    const int tid = threadIdx.x;
    const int pg = tid & 63, cg = tid >> 6;
    const int lx = (pg & 7) << 1, ly = (pg >> 3) << 1;

    if (NORM) {
        const int w = tid >> 5, lane = tid & 31;
#pragma unroll
        for (int c8 = 0; c8 < 8; c8++) {
            int c = (w << 3) + c8;
            float s = 0.f, q = 0.f;
            for (int t = lane; t < 512; t += 32) {
                s += ps_in[c * 512 + t];
                q += pq_in[c * 512 + t];
            }
#pragma unroll
            for (int d = 16; d >= 1; d >>= 1) {
                s += __shfl_down_sync(0xffffffffu, s, d);
                q += __shfl_down_sync(0xffffffffu, q, d);
            }
            if (lane == 0) {
                float mu = s * (1.f / UVE);
                s_mn[c] = mu;
                s_is[c] = rsqrtf(q * (1.f / UVE) - mu * mu + 1e-5f);
            }
        }
        __syncthreads();
    }

    ull acc[8][4];
#pragma unroll
    for (int cp = 0; cp < 8; cp++)
#pragma unroll
        for (int q = 0; q < 4; q++) acc[cp][q] = 0ull;

    float tv0, tv1 = 0.f;
    float wv0, wv1, wv2 = 0.f;
    {
        float mn = NORM ? s_mn[0] : 0.f, is = NORM ? s_is[0] : 1.f;
        tv0 = conv_val<NORM, RELU, 18>(in, 0, x0, y0, tid, mn, is);
        if (tid < 68) tv1 = conv_val<NORM, RELU, 18>(in, 0, x0, y0, tid + 256, mn, is);
        wv0 = wtf[tid]; wv1 = wtf[tid + 256];
        if (tid < 64) wv2 = wtf[tid + 512];
    }

    for (int cin = 0; cin < CIN; cin++) {
        const int b = cin & 1;
        tD[b][tid] = pack2(tv0, tv0);
        if (tid < 68) tD[b][tid + 256] = pack2(tv1, tv1);
        wsf[b][tid] = wv0; wsf[b][tid + 256] = wv1;
        if (tid < 64) wsf[b][tid + 512] = wv2;
        __syncthreads();
        if (cin + 1 < CIN) {
            int c2 = cin + 1;
            float mn = NORM ? s_mn[c2] : 0.f, is = NORM ? s_is[c2] : 1.f;
            tv0 = conv_val<NORM, RELU, 18>(in, c2, x0, y0, tid, mn, is);
            if (tid < 68) tv1 = conv_val<NORM, RELU, 18>(in, c2, x0, y0, tid + 256, mn, is);
            const float* wp = wtf + c2 * 576;
            wv0 = wp[tid]; wv1 = wp[tid + 256];
            if (tid < 64) wv2 = wp[tid + 512];
        }
        const ull* td = tD[b];
        const float* wk = wsf[b] + (cg << 4);
#pragma unroll
        for (int ky = 0; ky < 3; ky++) {
            ulonglong2 ra0 = *(const ulonglong2*)&td[(ly + ky) * 18 + lx];
            ulonglong2 ra1 = *(const ulonglong2*)&td[(ly + ky) * 18 + lx + 2];
            ulonglong2 rb0 = *(const ulonglong2*)&td[(ly + ky + 1) * 18 + lx];
            ulonglong2 rb1 = *(const ulonglong2*)&td[(ly + ky + 1) * 18 + lx + 2];
            ull pa[4] = { ra0.x, ra0.y, ra1.x, ra1.y };
            ull pb[4] = { rb0.x, rb0.y, rb1.x, rb1.y };
#pragma unroll
            for (int kx = 0; kx < 3; kx++) {
#pragma unroll
                for (int cp2 = 0; cp2 < 4; cp2++) {
                    ulonglong2 w2 = *(const ulonglong2*)&wk[(ky * 3 + kx) * 64 + (cp2 << 2)];
                    int ce = cp2 << 1;
                    acc[ce][0]     = fma2(pa[kx],     w2.x, acc[ce][0]);
                    acc[ce][1]     = fma2(pa[kx + 1], w2.x, acc[ce][1]);
                    acc[ce][2]     = fma2(pb[kx],     w2.x, acc[ce][2]);
                    acc[ce][3]     = fma2(pb[kx + 1], w2.x, acc[ce][3]);
                    acc[ce + 1][0] = fma2(pa[kx],     w2.y, acc[ce + 1][0]);
                    acc[ce + 1][1] = fma2(pa[kx + 1], w2.y, acc[ce + 1][1]);
                    acc[ce + 1][2] = fma2(pb[kx],     w2.y, acc[ce + 1][2]);
                    acc[ce + 1][3] = fma2(pb[kx + 1], w2.y, acc[ce + 1][3]);
                }
            }
        }
    }

    const int wpar = (tid >> 5) & 1;
#pragma unroll
    for (int cp = 0; cp < 8; cp++) {
        int cA = (cg << 4) + (cp << 1), cB = cA + 1;
        float bA = bias[cA], bB = bias[cB];
        float vA[4], vB[4];
#pragma unroll
        for (int q = 0; q < 4; q++) {
            unpack2(acc[cp][q], vA[q], vB[q]);
            vA[q] += bA; vB[q] += bB;
        }
        float* opA = out + cA * UVE + (y0 + ly) * 256 + (x0 + lx);
        float* opB = out + cB * UVE + (y0 + ly) * 256 + (x0 + lx);
        *(float2*)opA         = make_float2(vA[0], vA[1]);
        *(float2*)(opA + 256) = make_float2(vA[2], vA[3]);
        *(float2*)opB         = make_float2(vB[0], vB[1]);
        *(float2*)(opB + 256) = make_float2(vB[2], vB[3]);
        if (STATS) {
            float sA = vA[0] + vA[1] + vA[2] + vA[3];
            float qA = vA[0] * vA[0] + vA[1] * vA[1] + vA[2] * vA[2] + vA[3] * vA[3];
            float sB = vB[0] + vB[1] + vB[2] + vB[3];
            float qB = vB[0] * vB[0] + vB[1] * vB[1] + vB[2] * vB[2] + vB[3] * vB[3];
#pragma unroll
            for (int d = 16; d >= 1; d >>= 1) {
                sA += __shfl_down_sync(0xffffffffu, sA, d);
                qA += __shfl_down_sync(0xffffffffu, qA, d);
                sB += __shfl_down_sync(0xffffffffu, sB, d);
                qB += __shfl_down_sync(0xffffffffu, qB, d);
            }
            if ((tid & 31) == 0) {
                ps_out[cA * 512 + (bx << 1) + wpar] = sA;
                pq_out[cA * 512 + (bx << 1) + wpar] = qA;
                ps_out[cB * 512 + (bx << 1) + wpar] = sB;
                pq_out[cB * 512 + (bx << 1) + wpar] = qB;
            }
        }
    }
}

// conv_out: 64 -> 3, normalized input (prologue stats), sigmoid.
__global__ __launch_bounds__(256, 2)
void convout_k(const float* __restrict__ in, const float2* __restrict__ wt,
               const float* __restrict__ bias,
               const float* __restrict__ ps_in, const float* __restrict__ pq_in,
               float* __restrict__ out)
{
    __shared__ __align__(16) float tA[2][612];
    __shared__ __align__(16) float tB[2][616];
    __shared__ __align__(16) float2 wds[1728];
    __shared__ float s_mn[64], s_is[64];

    const int bx = blockIdx.x;
    const int x0 = (bx & 7) << 5, y0 = (bx >> 3) << 4;
    const int tid = threadIdx.x;
    const int lx = (tid & 15) << 1, ly = tid >> 4;

    {
        const int w = tid >> 5, lane = tid & 31;
#pragma unroll
        for (int c8 = 0; c8 < 8; c8++) {
            int c = (w << 3) + c8;
            float s = 0.f, q = 0.f;
            for (int t = lane; t < 512; t += 32) {
                s += ps_in[c * 512 + t];
                q += pq_in[c * 512 + t];
            }
#pragma unroll
            for (int d = 16; d >= 1; d >>= 1) {
                s += __shfl_down_sync(0xffffffffu, s, d);
                q += __shfl_down_sync(0xffffffffu, q, d);
            }
            if (lane == 0) {
                float mu = s * (1.f / UVE);
                s_mn[c] = mu;
                s_is[c] = rsqrtf(q * (1.f / UVE) - mu * mu + 1e-5f);
            }
        }
    }
    for (int e = tid; e < 1728; e += 256) wds[e] = wt[e];
    __syncthreads();

    ull acc0 = 0ull, acc1 = 0ull, acc2 = 0ull;

    float tv0, tv1 = 0.f, tv2 = 0.f;
    {
        float mn = s_mn[0], is = s_is[0];
        tv0 = conv_val<true, false, 34>(in, 0, x0, y0, tid, mn, is);
        tv1 = conv_val<true, false, 34>(in, 0, x0, y0, tid + 256, mn, is);
        if (tid < 100) tv2 = conv_val<true, false, 34>(in, 0, x0, y0, tid + 512, mn, is);
    }

    for (int cin = 0; cin < 64; cin++) {
        const int b = cin & 1;
        tA[b][tid] = tv0; tB[b][tid + 1] = tv0;
        tA[b][tid + 256] = tv1; tB[b][tid + 257] = tv1;
        if (tid < 100) { tA[b][tid + 512] = tv2; tB[b][tid + 513] = tv2; }
        __syncthreads();
        if (cin + 1 < 64) {
            int c2 = cin + 1;
            float mn = s_mn[c2], is = s_is[c2];
            tv0 = conv_val<true, false, 34>(in, c2, x0, y0, tid, mn, is);
            tv1 = conv_val<true, false, 34>(in, c2, x0, y0, tid + 256, mn, is);
            if (tid < 100) tv2 = conv_val<true, false, 34>(in, c2, x0, y0, tid + 512, mn, is);
        }
        ull pp[3][3];
#pragma unroll
        for (int r = 0; r < 3; r++) {
            int base = (ly + r) * 34 + lx;
            pp[r][0] = *(const ull*)&tA[b][base];
            pp[r][1] = *(const ull*)&tB[b][base + 2];
            pp[r][2] = *(const ull*)&tA[b][base + 2];
        }
        const float2* wc = wds + cin * 27;
#pragma unroll
        for (int r = 0; r < 3; r++)
#pragma unroll
            for (int kx = 0; kx < 3; kx++) {
                acc0 = fma2(pp[r][kx], *(const ull*)&wc[r * 3 + kx],      acc0);
                acc1 = fma2(pp[r][kx], *(const ull*)&wc[9 + r * 3 + kx],  acc1);
                acc2 = fma2(pp[r][kx], *(const ull*)&wc[18 + r * 3 + kx], acc2);
            }
        __syncthreads();
    }

    int o = (y0 + ly) * 256 + x0 + lx;
    float lo, hi;
    unpack2(acc0, lo, hi);
    *(float2*)(out + o) = make_float2(1.f / (1.f + __expf(-(lo + bias[0]))),
                                      1.f / (1.f + __expf(-(hi + bias[0]))));
    unpack2(acc1, lo, hi);
    *(float2*)(out + UVE + o) = make_float2(1.f / (1.f + __expf(-(lo + bias[1]))),
                                            1.f / (1.f + __expf(-(hi + bias[1]))));
    unpack2(acc2, lo, hi);
    *(float2*)(out + 2 * UVE + o) = make_float2(1.f / (1.f + __expf(-(lo + bias[2]))),
                                                1.f / (1.f + __expf(-(hi + bias[2]))));
}

// ---------- launch ----------
extern "C" void kernel_launch(void* const* d_in, const int* in_sizes, int n_in,
                              void* d_out, int out_size)
{
    const float* latent_z  = (const float*)d_in[0];
    const float* latent_f  = (const float*)d_in[1];
    const float* cano_xyz  = (const float*)d_in[2];
    const float* m1_w_in   = (const float*)d_in[3];
    const float* m1_b_in   = (const float*)d_in[4];
    const float* m1_w_hid  = (const float*)d_in[5];
    const float* m1_b_hid  = (const float*)d_in[6];
    const float* m1_w_out  = (const float*)d_in[7];
    const float* m1_b_out  = (const float*)d_in[8];
    const float* m2_w_in   = (const float*)d_in[9];
    const float* m2_b_in   = (const float*)d_in[10];
    const float* m2_w_hid  = (const float*)d_in[11];
    const float* m2_b_hid  = (const float*)d_in[12];
    const float* m2_w_out  = (const float*)d_in[13];
    const float* m2_b_out  = (const float*)d_in[14];
    const float* conv_in_w = (const float*)d_in[15];
    const float* conv_in_b = (const float*)d_in[16];
    const float* conv_hid_w= (const float*)d_in[17];
    const float* conv_hid_b= (const float*)d_in[18];
    const float* conv_out_w= (const float*)d_in[19];
    const float* conv_out_b= (const float*)d_in[20];
    const int*   gs_part   = (const int*)d_in[21];
    const int*   uv_idx    = (const int*)d_in[22];
    float* outp = (float*)d_out;

    void *p_counts, *p_offsets, *p_cursor, *p_order, *p_uvmap, *p_bufA, *p_bufB;
    void *p_wtf, *p_wt, *p_psA, *p_pqA, *p_psB, *p_pqB;
    cudaGetSymbolAddress(&p_counts, g_counts);
    cudaGetSymbolAddress(&p_offsets, g_offsets);
    cudaGetSymbolAddress(&p_cursor, g_cursor);
    cudaGetSymbolAddress(&p_order, g_order);
    cudaGetSymbolAddress(&p_uvmap, g_uvmap);
    cudaGetSymbolAddress(&p_bufA, g_bufA);
    cudaGetSymbolAddress(&p_bufB, g_bufB);
    cudaGetSymbolAddress(&p_wtf, g_wtf);
    cudaGetSymbolAddress(&p_wt, g_wt);
    cudaGetSymbolAddress(&p_psA, g_psumA);
    cudaGetSymbolAddress(&p_pqA, g_psumsqA);
    cudaGetSymbolAddress(&p_psB, g_psumB);
    cudaGetSymbolAddress(&p_pqB, g_psumsqB);

    // Order chosen so mlp_k is the 6th launch (ncu -s 5 -c 1 profiles it).
    cudaMemsetAsync(p_uvmap, 0, 32 * UVE * sizeof(float), 0);
    cudaMemsetAsync(p_counts, 0, 8 * sizeof(int), 0);

    int gb = (GN + 255) / 256;
    count_k<<<gb, 256>>>(gs_part, (int*)p_counts);
    scan_k<<<1, 32>>>((const int*)p_counts, (int*)p_offsets, (int*)p_cursor);
    scatter_k<<<gb, 256>>>(gs_part, (int*)p_cursor, (int*)p_order);

    static bool attr_set = false;
    if (!attr_set) {
        cudaFuncSetAttribute(mlp_k, cudaFuncAttributeMaxDynamicSharedMemorySize, 111104);
        attr_set = true;
    }
    mlp_k<<<PN * NT, 256, 111104>>>(
        latent_z, latent_f, cano_xyz,
        m1_w_in, m1_b_in, m1_w_hid, m1_b_hid, m1_w_out, m1_b_out,
        m2_w_in, m2_b_in, m2_w_hid, m2_b_hid, m2_w_out, m2_b_out,
        uv_idx, (const int*)p_order, (const int*)p_offsets, (float*)p_uvmap);

    wprep_k<<<432, 256>>>(conv_in_w, conv_hid_w, conv_out_w, (float*)p_wtf, (float2*)p_wt);

    float* bufA = (float*)p_bufA;
    float* bufB = (float*)p_bufB;
    float* psA = (float*)p_psA; float* pqA = (float*)p_pqA;
    float* psB = (float*)p_psB; float* pqB = (float*)p_pqB;
    const float* wtf = (const float*)p_wtf;

    conv64_k<32, false, false, false><<<256, 256>>>((const float*)p_uvmap, wtf, conv_in_b, 0, 0, bufA, 0, 0);
    conv64_k<64, true, false, true><<<256, 256>>>(bufA, wtf + 18432, conv_hid_b, 0, 0, bufB, psA, pqA);
    conv64_k<64, true, true, true><<<256, 256>>>(bufB, wtf + 18432 + 36864, conv_hid_b + 64, psA, pqA, bufA, psB, pqB);
    conv64_k<64, true, true, true><<<256, 256>>>(bufA, wtf + 18432 + 2 * 36864, conv_hid_b + 128, psB, pqB, bufB, psA, pqA);
    convout_k<<<128, 256>>>(bufB, (const float2*)p_wt, conv_out_b, psA, pqA, outp);
}